// round 4
// baseline (speedup 1.0000x reference)
#include <cuda_runtime.h>
#include <cstdint>

#define Bn   32
#define Tn   64
#define Nn   128
#define Dn   64
#define Cn   129
#define CP   132      // padded C (multiple of 4)
#define CKn  16
#define Hn   2
#define QDn  5
#define NEn  8
#define PLMn 768
#define G3   192      // rst(64) | upd(64) | cand(64)
#define NEGV (-9e15f)

// ---------------- device scratch (static, no runtime alloc) ----------------
__device__ __align__(16) float g_qv[Nn * QDn];
__device__ __align__(16) float g_ne[Nn * NEn];
__device__ __align__(16) float g_adj[Nn * Nn];
__device__ __align__(16) float g_vto[Bn * Nn];
__device__ __align__(16) float g_rar[Bn * Tn * Nn];
__device__ __align__(16) float g_gW[Nn * Cn * G3];     // per-node gate weights  (~12.7MB)
__device__ __align__(16) float g_gB[Nn * G3];
__device__ __align__(16) float g_WT[322 * CP];         // qkv weights, transposed + padded
__device__ __align__(16) float g_bT[322];
__device__ __align__(16) float g_h[Bn * Nn * Dn];
__device__ __align__(16) float g_Q[Bn * Hn * Nn * CKn];
__device__ __align__(16) float g_K[Bn * Hn * Nn * CKn];
__device__ __align__(16) float g_V[Bn * Hn * Nn * Cn];
__device__ __align__(16) float g_att[Bn * Nn * CP];    // head-mean attention output (padded rows)

// ---------------- precompute kernels ----------------

__global__ void k_zero_h() {
    int i = blockIdx.x * 256 + threadIdx.x;
    if (i < Bn * Nn * Dn) g_h[i] = 0.0f;
}

// var_total_obs + rarity score for all timesteps
__global__ void k_pre0(const float* __restrict__ maskp, const float* __restrict__ avg) {
    int b = blockIdx.x, n = threadIdx.x;   // 128 threads
    float s = 0.0f;
    for (int t = 0; t < Tn; t++) s += maskp[(b * Tn + t) * Nn + n];
    g_vto[b * Nn + n] = s;
    float inv = 1.0f / (s + 1.0f);
    for (int t = 0; t < Tn; t++)
        g_rar[(b * Tn + t) * Nn + n] = 0.5f * tanhf(avg[(b * Tn + t) * Nn + n] * inv);
}

// qv (query vectors) and normalized node embeddings
__global__ void k_pre1(const float* __restrict__ plm,
                       const float* __restrict__ pfW1, const float* __restrict__ pfb1,
                       const float* __restrict__ pfW2, const float* __restrict__ pfb2,
                       const float* __restrict__ pgW1, const float* __restrict__ pgb1,
                       const float* __restrict__ pgW2, const float* __restrict__ pgb2) {
    int n = blockIdx.x, j = threadIdx.x;   // 128 threads
    __shared__ float h1[128], h2[128];
    __shared__ float nrm;
    const float* p = plm + (size_t)n * PLMn;
    float a = 0.0f, bv = 0.0f;
    for (int c = 0; c < PLMn; c++) {
        float pv = p[c];
        a  += pv * pfW1[c * 128 + j];
        bv += pv * pgW1[c * 128 + j];
    }
    a += pfb1[j]; bv += pgb1[j];
    h1[j] = a  > 0.0f ? a  : 0.0f;
    h2[j] = bv > 0.0f ? bv : 0.0f;
    __syncthreads();
    if (j < QDn) {
        float s = pfb2[j];
        for (int c = 0; c < 128; c++) s += h1[c] * pfW2[c * QDn + j];
        g_qv[n * QDn + j] = s;
    }
    if (j < NEn) {
        float s = pgb2[j];
        for (int c = 0; c < 128; c++) s += h2[c] * pgW2[c * NEn + j];
        g_ne[n * NEn + j] = s;
    }
    __syncthreads();
    if (j == 0) {
        float s = 0.0f;
        for (int e = 0; e < NEn; e++) { float v = g_ne[n * NEn + e]; s += v * v; }
        nrm = fmaxf(sqrtf(s), 1e-12f);
    }
    __syncthreads();
    if (j < NEn) g_ne[n * NEn + j] /= nrm;
}

// static base adjacency: softmax(ne @ ne^T)
__global__ void k_pre2() {
    int n = blockIdx.x, m = threadIdx.x;   // 128 threads
    __shared__ float red[128];
    float s = 0.0f;
    for (int e = 0; e < NEn; e++) s += g_ne[n * NEn + e] * g_ne[m * NEn + e];
    red[m] = s;
    __syncthreads();
    for (int st = 64; st > 0; st >>= 1) { if (m < st) red[m] = fmaxf(red[m], red[m + st]); __syncthreads(); }
    float mx = red[0];
    __syncthreads();
    float e = expf(s - mx);
    red[m] = e;
    __syncthreads();
    for (int st = 64; st > 0; st >>= 1) { if (m < st) red[m] += red[m + st]; __syncthreads(); }
    g_adj[n * Nn + m] = e / red[0];
}

// per-node gate weights/biases: Wn = sum_q qv[n,q] * W[q]
__global__ void k_pre3(const float* __restrict__ rstW, const float* __restrict__ rstB,
                       const float* __restrict__ updW, const float* __restrict__ updB,
                       const float* __restrict__ candW, const float* __restrict__ candB) {
    int n = blockIdx.x;
    __shared__ float qv[QDn];
    if (threadIdx.x < QDn) qv[threadIdx.x] = g_qv[n * QDn + threadIdx.x];
    __syncthreads();
    for (int idx = threadIdx.x; idx < Cn * Dn; idx += blockDim.x) {
        int c = idx / Dn, o = idx % Dn;
        float r = 0.0f, u = 0.0f, cd = 0.0f;
        for (int q = 0; q < QDn; q++) {
            float s = qv[q];
            int off = (q * Cn + c) * Dn + o;
            r  += s * rstW[off];
            u  += s * updW[off];
            cd += s * candW[off];
        }
        float* dst = g_gW + ((size_t)n * Cn + c) * G3;
        dst[o] = r; dst[64 + o] = u; dst[128 + o] = cd;
    }
    for (int o = threadIdx.x; o < Dn; o += blockDim.x) {
        float r = 0.0f, u = 0.0f, cd = 0.0f;
        for (int q = 0; q < QDn; q++) {
            float s = qv[q];
            r  += s * rstB[q * Dn + o];
            u  += s * updB[q * Dn + o];
            cd += s * candB[q * Dn + o];
        }
        g_gB[n * G3 + o] = r; g_gB[n * G3 + 64 + o] = u; g_gB[n * G3 + 128 + o] = cd;
    }
}

// transpose qkv weights into [out=322][c padded to 132]
__global__ void k_pre4(const float* __restrict__ qW, const float* __restrict__ qb,
                       const float* __restrict__ kW, const float* __restrict__ kb,
                       const float* __restrict__ vW, const float* __restrict__ vb) {
    int j = blockIdx.x;      // 322 outputs
    int c = threadIdx.x;     // 132 threads
    float w = 0.0f, bv = 0.0f;
    if (j < 32)      { int h = j / CKn, kk = j % CKn; if (c < Cn) w = qW[(h * Cn + c) * CKn + kk]; bv = qb[h * CKn + kk]; }
    else if (j < 64) { int jj = j - 32; int h = jj / CKn, kk = jj % CKn; if (c < Cn) w = kW[(h * Cn + c) * CKn + kk]; bv = kb[h * CKn + kk]; }
    else             { int jj = j - 64; int h = jj / Cn, d = jj % Cn;   if (c < Cn) w = vW[(h * Cn + c) * Cn + d];   bv = vb[h * Cn + d]; }
    g_WT[j * CP + c] = w;
    if (c == 0) g_bT[j] = bv;
}

// ---------------- per-step kernels ----------------

// K1: comb = [obs, rar, h] -> q,k,v.  grid (4, B), 256 threads
__global__ void __launch_bounds__(256) k_qkv(const float* __restrict__ obs, int t) {
    __shared__ __align__(16) float comb[32][CP];
    int b = blockIdx.y, n0 = blockIdx.x * 32, tid = threadIdx.x;
    for (int idx = tid; idx < 32 * CP; idx += 256) {
        int rr = idx / CP, c = idx - rr * CP;
        int n = n0 + rr;
        float v = 0.0f;
        if (c < Dn)       v = obs[(((size_t)b * Tn + t) * Nn + n) * Dn + c];
        else if (c == Dn) v = g_rar[(b * Tn + t) * Nn + n];
        else if (c < Cn)  v = g_h[((size_t)b * Nn + n) * Dn + (c - Dn - 1)];
        comb[rr][c] = v;
    }
    __syncthreads();
    int warp = tid >> 5, lane = tid & 31;
    const float4* cp = (const float4*)(&comb[lane][0]);
    for (int j = warp; j < 322; j += 8) {
        const float4* wp = (const float4*)(g_WT + j * CP);
        float a0 = 0, a1 = 0, a2 = 0, a3 = 0;
        #pragma unroll
        for (int c4 = 0; c4 < 33; c4++) {
            float4 w = wp[c4], x = cp[c4];
            a0 += w.x * x.x; a1 += w.y * x.y; a2 += w.z * x.z; a3 += w.w * x.w;
        }
        float acc = (a0 + a1) + (a2 + a3) + g_bT[j];
        int n = n0 + lane;
        if (j < 64) {
            int h = (j >> 4) & 1, kk = j & 15;
            float* dst = (j < 32) ? g_Q : g_K;
            dst[((b * 2 + h) * Nn + n) * CKn + kk] = acc;
        } else {
            int jj = j - 64;
            int h = jj / Cn, d = jj - h * Cn;
            g_V[(((size_t)b * 2 + h) * Nn + n) * Cn + d] = acc;
        }
    }
}

// K2: masked leaky attention + softmax + P@V, head-mean.  grid (4, B), 256 threads
#define ATTN_SMEM ((128*132 + 32*132 + 128*17 + 32*17 + 128 + 128) * 4 + 32*128)
__global__ void __launch_bounds__(256) k_attn(const float* __restrict__ maskp,
                                              const float* __restrict__ rarW, int t) {
    extern __shared__ float sm[];
    float* Vs  = sm;                 // 128*132
    float* Ss  = Vs + 128 * 132;     // 32*132
    float* Ks  = Ss + 32 * 132;      // 128*17
    float* qs  = Ks + 128 * 17;      // 32*17
    float* rs  = qs + 32 * 17;       // 128
    float* msv = rs + 128;           // 128
    unsigned char* mskb = (unsigned char*)(msv + 128);  // 32*128

    int b = blockIdx.y, n0 = blockIdx.x * 32, tid = threadIdx.x;
    int r = tid >> 3, c8 = tid & 7;

    if (tid < 128) {
        rs[tid]  = g_rar[(b * Tn + t) * Nn + tid];
        msv[tid] = maskp[(b * Tn + t) * Nn + tid];
    }
    __syncthreads();
    // mask predicate (shared across heads): cur_adj == 0 ?
    for (int idx = tid; idx < 32 * 128; idx += 256) {
        int rr = idx >> 7, m = idx & 127;
        int n = n0 + rr;
        unsigned char km = 0;
        if (n != m) {
            float am  = msv[n] * msv[m];
            float rm  = -rarW[n * Nn + m] * fabsf(rs[n] - rs[m]);
            float val = g_adj[n * Nn + m] * (1.0f + rm) * am;
            km = (val == 0.0f) ? 1 : 0;
        }
        mskb[idx] = km;
    }

    float4 acc[5];
    #pragma unroll
    for (int j = 0; j < 5; j++) acc[j] = make_float4(0, 0, 0, 0);

    for (int h = 0; h < 2; h++) {
        __syncthreads();   // mskb ready / previous head's Ss,Vs reads done
        for (int idx = tid; idx < 128 * 16; idx += 256) {
            int m = idx >> 4, kk = idx & 15;
            Ks[m * 17 + kk] = g_K[((b * 2 + h) * Nn + m) * CKn + kk];
        }
        for (int idx = tid; idx < 32 * 16; idx += 256) {
            int rr = idx >> 4, kk = idx & 15;
            qs[rr * 17 + kk] = g_Q[((b * 2 + h) * Nn + n0 + rr) * CKn + kk];
        }
        for (int idx = tid; idx < 128 * 132; idx += 256) {
            int m = idx / 132, c = idx - m * 132;
            Vs[idx] = (c < Cn) ? g_V[(((size_t)b * 2 + h) * Nn + m) * Cn + c] : 0.0f;
        }
        __syncthreads();

        float qr[16];
        #pragma unroll
        for (int kk = 0; kk < 16; kk++) qr[kk] = qs[r * 17 + kk];

        float sv[16];
        float mx = -1e30f;
        #pragma unroll
        for (int jm = 0; jm < 16; jm++) {
            int m = c8 + 8 * jm;
            float d = 0.0f;
            #pragma unroll
            for (int kk = 0; kk < 16; kk++) d += qr[kk] * Ks[m * 17 + kk];
            d *= 0.25f;
            d = d > 0.0f ? d : 0.2f * d;            // leaky_relu(0.2)
            if (mskb[(r << 7) + m]) d = NEGV;       // adjacency mask
            sv[jm] = d;
            mx = fmaxf(mx, d);
        }
        #pragma unroll
        for (int o = 1; o < 8; o <<= 1) mx = fmaxf(mx, __shfl_xor_sync(0xffffffffu, mx, o));
        float sum = 0.0f;
        #pragma unroll
        for (int jm = 0; jm < 16; jm++) { float e = __expf(sv[jm] - mx); sv[jm] = e; sum += e; }
        #pragma unroll
        for (int o = 1; o < 8; o <<= 1) sum += __shfl_xor_sync(0xffffffffu, sum, o);
        float inv = 1.0f / sum;
        #pragma unroll
        for (int jm = 0; jm < 16; jm++) Ss[r * 132 + c8 + 8 * jm] = sv[jm] * inv;
        __syncthreads();

        const float4* Vs4 = (const float4*)Vs;
        for (int m = 0; m < 128; m++) {
            float p = Ss[r * 132 + m];
            #pragma unroll
            for (int j = 0; j < 4; j++) {
                float4 v = Vs4[m * 33 + c8 + 8 * j];
                acc[j].x += p * v.x; acc[j].y += p * v.y; acc[j].z += p * v.z; acc[j].w += p * v.w;
            }
            if (c8 == 0) {
                float4 v = Vs4[m * 33 + 32];
                acc[4].x += p * v.x; acc[4].y += p * v.y; acc[4].z += p * v.z; acc[4].w += p * v.w;
            }
        }
    }
    float4* Ao = (float4*)(g_att + ((size_t)b * Nn + n0 + r) * CP);
    #pragma unroll
    for (int j = 0; j < 4; j++) {
        float4 a = acc[j];
        a.x *= 0.5f; a.y *= 0.5f; a.z *= 0.5f; a.w *= 0.5f;
        Ao[c8 + 8 * j] = a;
    }
    if (c8 == 0) {
        float4 a = acc[4];
        a.x *= 0.5f; a.y *= 0.5f; a.z *= 0.5f; a.w *= 0.5f;
        Ao[32] = a;
    }
}

// K3: per-node GRU gates for all 32 batches.  grid N, 256 threads
#define GATE_SMEM ((Cn*G3 + 32*132 + 32*64 + 32*64 + G3 + 32) * 4)
__global__ void __launch_bounds__(256) k_gate(const float* __restrict__ obs,
                                              const float* __restrict__ maskp,
                                              const int* __restrict__ lengths,
                                              float* __restrict__ out, int t) {
    extern __shared__ float sm[];
    float* Wn  = sm;                 // 129*192
    float* zs  = Wn + Cn * G3;       // 32*132
    float* h1s = zs + 32 * 132;      // 32*64
    float* us  = h1s + 32 * 64;      // 32*64
    float* gb  = us + 32 * 64;       // 192
    float* ms2 = gb + G3;            // 32

    int n = blockIdx.x, tid = threadIdx.x;

    const float4* srcw = (const float4*)(g_gW + (size_t)n * Cn * G3);
    float4* dstw = (float4*)Wn;
    for (int idx = tid; idx < Cn * G3 / 4; idx += 256) dstw[idx] = srcw[idx];
    for (int idx = tid; idx < G3; idx += 256) gb[idx] = g_gB[n * G3 + idx];
    if (tid < 32) ms2[tid] = maskp[((size_t)tid * Tn + t) * Nn + n];
    for (int idx = tid; idx < 32 * 132; idx += 256) {
        int bb2 = idx / 132, c = idx - bb2 * 132;
        zs[idx] = g_att[((size_t)bb2 * Nn + n) * CP + c];
    }
    __syncthreads();

    int bb = tid >> 3, c8 = tid & 7;
    float mval = ms2[bb];
    bool ob = (mval > 0.0f);

    // r,u gemm: outputs o = 0..127 (float4 chunks c8+8j, j<4)
    float4 a[4];
    #pragma unroll
    for (int j = 0; j < 4; j++) a[j] = make_float4(0, 0, 0, 0);
    for (int c = 0; c < Cn; c++) {
        float z = zs[bb * 132 + c];
        const float4* w4 = (const float4*)(Wn + c * G3);
        #pragma unroll
        for (int j = 0; j < 4; j++) {
            float4 w = w4[c8 + 8 * j];
            a[j].x += z * w.x; a[j].y += z * w.y; a[j].z += z * w.z; a[j].w += z * w.w;
        }
    }
    #pragma unroll
    for (int j = 0; j < 4; j++) {
        int o0 = (c8 + 8 * j) * 4;
        float vv[4] = { a[j].x, a[j].y, a[j].z, a[j].w };
        #pragma unroll
        for (int e = 0; e < 4; e++) {
            int o = o0 + e;
            float g = 1.0f / (1.0f + __expf(-(vv[e] + gb[o])));
            if (o < 64) {
                float hv = g_h[((size_t)bb * Nn + n) * Dn + o];
                h1s[bb * 64 + o] = ob ? g * hv : hv;
            } else {
                us[bb * 64 + (o - 64)] = g;
            }
        }
    }
    __syncthreads();

    // comb2 = [x, h1]
    for (int idx = tid; idx < 32 * 132; idx += 256) {
        int b2 = idx / 132, c = idx - b2 * 132;
        float v = 0.0f;
        if (c < Dn)       v = obs[(((size_t)b2 * Tn + t) * Nn + n) * Dn + c];
        else if (c == Dn) v = g_rar[(b2 * Tn + t) * Nn + n];
        else if (c < Cn)  v = h1s[b2 * 64 + (c - Dn - 1)];
        zs[idx] = v;
    }
    __syncthreads();

    // cand gemm: outputs o = 0..63 (float4 chunks c8+8j, j<2)
    float4 b2a[2];
    b2a[0] = make_float4(0, 0, 0, 0); b2a[1] = make_float4(0, 0, 0, 0);
    for (int c = 0; c < Cn; c++) {
        float z = zs[bb * 132 + c];
        const float4* w4 = (const float4*)(Wn + c * G3 + 128);
        #pragma unroll
        for (int j = 0; j < 2; j++) {
            float4 w = w4[c8 + 8 * j];
            b2a[j].x += z * w.x; b2a[j].y += z * w.y; b2a[j].z += z * w.z; b2a[j].w += z * w.w;
        }
    }
    bool fin = (t == lengths[bb] - 1);
    #pragma unroll
    for (int j = 0; j < 2; j++) {
        int o0 = (c8 + 8 * j) * 4;
        float vv[4] = { b2a[j].x, b2a[j].y, b2a[j].z, b2a[j].w };
        #pragma unroll
        for (int e = 0; e < 4; e++) {
            int d = o0 + e;
            float cand = tanhf(vv[e] + gb[128 + d]);
            float h1 = h1s[bb * 64 + d];
            float u  = us[bb * 64 + d];
            float h2 = ob ? (1.0f - u) * h1 + u * cand : h1;
            g_h[((size_t)bb * Nn + n) * Dn + d] = h2;
            if (fin) out[((size_t)bb * Nn + n) * Dn + d] = h2;
        }
    }
}

// ---------------- launcher ----------------
extern "C" void kernel_launch(void* const* d_in, const int* in_sizes, int n_in,
                              void* d_out, int out_size) {
    (void)n_in; (void)out_size;
    const float* obs   = (const float*)d_in[0];
    const float* maskp = (const float*)d_in[1];
    const float* avg   = (const float*)d_in[2];
    const float* plm   = (const float*)d_in[3];
    const int* lengths;
    int off;
    if (in_sizes[4] == Bn) { lengths = (const int*)d_in[4];  off = 5; }   // setup_inputs dict order
    else                   { lengths = (const int*)d_in[25]; off = 4; }   // reference signature order
    const float* rarW  = (const float*)d_in[off + 0];
    const float* pfW1  = (const float*)d_in[off + 1];
    const float* pfb1  = (const float*)d_in[off + 2];
    const float* pfW2  = (const float*)d_in[off + 3];
    const float* pfb2  = (const float*)d_in[off + 4];
    const float* pgW1  = (const float*)d_in[off + 5];
    const float* pgb1  = (const float*)d_in[off + 6];
    const float* pgW2  = (const float*)d_in[off + 7];
    const float* pgb2  = (const float*)d_in[off + 8];
    const float* rstW  = (const float*)d_in[off + 9];
    const float* rstB  = (const float*)d_in[off + 10];
    const float* updW  = (const float*)d_in[off + 11];
    const float* updB  = (const float*)d_in[off + 12];
    const float* candW = (const float*)d_in[off + 13];
    const float* candB = (const float*)d_in[off + 14];
    const float* qW    = (const float*)d_in[off + 15];
    const float* qb    = (const float*)d_in[off + 16];
    const float* kW    = (const float*)d_in[off + 17];
    const float* kb    = (const float*)d_in[off + 18];
    const float* vW    = (const float*)d_in[off + 19];
    const float* vb    = (const float*)d_in[off + 20];
    float* out = (float*)d_out;

    cudaFuncSetAttribute(k_attn, cudaFuncAttributeMaxDynamicSharedMemorySize, ATTN_SMEM);
    cudaFuncSetAttribute(k_gate, cudaFuncAttributeMaxDynamicSharedMemorySize, GATE_SMEM);

    k_zero_h<<<(Bn * Nn * Dn + 255) / 256, 256>>>();
    k_pre0<<<Bn, Nn>>>(maskp, avg);
    k_pre1<<<Nn, 128>>>(plm, pfW1, pfb1, pfW2, pfb2, pgW1, pgb1, pgW2, pgb2);
    k_pre2<<<Nn, Nn>>>();
    k_pre3<<<Nn, 256>>>(rstW, rstB, updW, updB, candW, candB);
    k_pre4<<<322, CP>>>(qW, qb, kW, kb, vW, vb);

    for (int t = 0; t < Tn; t++) {
        k_qkv <<<dim3(4, Bn), 256>>>(obs, t);
        k_attn<<<dim3(4, Bn), 256, ATTN_SMEM>>>(maskp, rarW, t);
        k_gate<<<Nn, 256, GATE_SMEM>>>(obs, maskp, lengths, out, t);
    }
}

// round 5
// speedup vs baseline: 1.3456x; 1.3456x over previous
#include <cuda_runtime.h>
#include <cstdint>

#define Bn   32
#define Tn   64
#define Nn   128
#define Dn   64
#define Cn   129
#define CP   132      // padded C (multiple of 4)
#define CKn  16
#define QDn  5
#define NEn  8
#define PLMn 768
#define G3   192      // rst(64) | upd(64) | cand(64)
#define NEGV (-9e15f)

#define WCOLS 352     // 322 qkv outputs padded to 352 (44 float4 chunks, 11 per c8 lane)
#define NCTA  128u

// ---------------- device scratch (static, no runtime alloc) ----------------
__device__ __align__(16) float g_qv[Nn * QDn];
__device__ __align__(16) float g_ne[Nn * NEn];
__device__ __align__(16) float g_adj[Nn * Nn];
__device__ __align__(16) float g_rar[Bn * Tn * Nn];
__device__ __align__(16) float g_gW[Nn * Cn * G3];     // per-node gate weights (~12.7MB)
__device__ __align__(16) float g_gB[Nn * G3];
__device__ __align__(16) float g_WT2[Cn * WCOLS];      // qkv weights, c-major, padded
__device__ __align__(16) float g_bT[WCOLS];
__device__ __align__(16) float g_h[Bn * Nn * Dn];
__device__ __align__(16) float g_K[Bn * 2 * Nn * CKn];
__device__ __align__(16) float g_V[Bn * 2 * Nn * CP];
__device__ __align__(16) float g_att[Bn * Nn * CP];

// grid barrier state
__device__ unsigned g_bar_cnt;
__device__ volatile unsigned g_bar_gen;

// ---------------- precompute kernels ----------------

__global__ void k_reset() {
    int i = blockIdx.x * 256 + threadIdx.x;
    if (i < Bn * Nn * Dn) g_h[i] = 0.0f;
    if (i == 0) { g_bar_cnt = 0; g_bar_gen = 0; }
}

__global__ void k_pre0(const float* __restrict__ maskp, const float* __restrict__ avg) {
    int b = blockIdx.x, n = threadIdx.x;   // 128 threads
    float s = 0.0f;
    for (int t = 0; t < Tn; t++) s += maskp[(b * Tn + t) * Nn + n];
    float inv = 1.0f / (s + 1.0f);
    for (int t = 0; t < Tn; t++)
        g_rar[(b * Tn + t) * Nn + n] = 0.5f * tanhf(avg[(b * Tn + t) * Nn + n] * inv);
}

__global__ void k_pre1(const float* __restrict__ plm,
                       const float* __restrict__ pfW1, const float* __restrict__ pfb1,
                       const float* __restrict__ pfW2, const float* __restrict__ pfb2,
                       const float* __restrict__ pgW1, const float* __restrict__ pgb1,
                       const float* __restrict__ pgW2, const float* __restrict__ pgb2) {
    int n = blockIdx.x, j = threadIdx.x;   // 128 threads
    __shared__ float h1[128], h2[128];
    __shared__ float nrm;
    const float* p = plm + (size_t)n * PLMn;
    float a = 0.0f, bv = 0.0f;
    for (int c = 0; c < PLMn; c++) {
        float pv = p[c];
        a  += pv * pfW1[c * 128 + j];
        bv += pv * pgW1[c * 128 + j];
    }
    a += pfb1[j]; bv += pgb1[j];
    h1[j] = a  > 0.0f ? a  : 0.0f;
    h2[j] = bv > 0.0f ? bv : 0.0f;
    __syncthreads();
    if (j < QDn) {
        float s = pfb2[j];
        for (int c = 0; c < 128; c++) s += h1[c] * pfW2[c * QDn + j];
        g_qv[n * QDn + j] = s;
    }
    if (j < NEn) {
        float s = pgb2[j];
        for (int c = 0; c < 128; c++) s += h2[c] * pgW2[c * NEn + j];
        g_ne[n * NEn + j] = s;
    }
    __syncthreads();
    if (j == 0) {
        float s = 0.0f;
        for (int e = 0; e < NEn; e++) { float v = g_ne[n * NEn + e]; s += v * v; }
        nrm = fmaxf(sqrtf(s), 1e-12f);
    }
    __syncthreads();
    if (j < NEn) g_ne[n * NEn + j] /= nrm;
}

__global__ void k_pre2() {
    int n = blockIdx.x, m = threadIdx.x;   // 128 threads
    __shared__ float red[128];
    float s = 0.0f;
    for (int e = 0; e < NEn; e++) s += g_ne[n * NEn + e] * g_ne[m * NEn + e];
    red[m] = s;
    __syncthreads();
    for (int st = 64; st > 0; st >>= 1) { if (m < st) red[m] = fmaxf(red[m], red[m + st]); __syncthreads(); }
    float mx = red[0];
    __syncthreads();
    float e = expf(s - mx);
    red[m] = e;
    __syncthreads();
    for (int st = 64; st > 0; st >>= 1) { if (m < st) red[m] += red[m + st]; __syncthreads(); }
    g_adj[n * Nn + m] = e / red[0];
}

__global__ void k_pre3(const float* __restrict__ rstW, const float* __restrict__ rstB,
                       const float* __restrict__ updW, const float* __restrict__ updB,
                       const float* __restrict__ candW, const float* __restrict__ candB) {
    int n = blockIdx.x;
    __shared__ float qv[QDn];
    if (threadIdx.x < QDn) qv[threadIdx.x] = g_qv[n * QDn + threadIdx.x];
    __syncthreads();
    for (int idx = threadIdx.x; idx < Cn * Dn; idx += blockDim.x) {
        int c = idx / Dn, o = idx % Dn;
        float r = 0.0f, u = 0.0f, cd = 0.0f;
        for (int q = 0; q < QDn; q++) {
            float s = qv[q];
            int off = (q * Cn + c) * Dn + o;
            r  += s * rstW[off];
            u  += s * updW[off];
            cd += s * candW[off];
        }
        float* dst = g_gW + ((size_t)n * Cn + c) * G3;
        dst[o] = r; dst[64 + o] = u; dst[128 + o] = cd;
    }
    for (int o = threadIdx.x; o < Dn; o += blockDim.x) {
        float r = 0.0f, u = 0.0f, cd = 0.0f;
        for (int q = 0; q < QDn; q++) {
            float s = qv[q];
            r  += s * rstB[q * Dn + o];
            u  += s * updB[q * Dn + o];
            cd += s * candB[q * Dn + o];
        }
        g_gB[n * G3 + o] = r; g_gB[n * G3 + 64 + o] = u; g_gB[n * G3 + 128 + o] = cd;
    }
}

// qkv weights -> c-major padded matrix [129][352]
__global__ void k_pre4(const float* __restrict__ qW, const float* __restrict__ qb,
                       const float* __restrict__ kW, const float* __restrict__ kb,
                       const float* __restrict__ vW, const float* __restrict__ vb) {
    int c = blockIdx.x;       // 0..128
    int j = threadIdx.x;      // 0..351
    float w = 0.0f, bv = 0.0f;
    if (j < 32)       { int h = j >> 4, kk = j & 15;               w = qW[(h * Cn + c) * CKn + kk]; bv = qb[h * CKn + kk]; }
    else if (j < 64)  { int jj = j - 32; int h = jj >> 4, kk = jj & 15; w = kW[(h * Cn + c) * CKn + kk]; bv = kb[h * CKn + kk]; }
    else if (j < 322) { int jj = j - 64; int h = jj >= Cn; int d = jj - h * Cn; w = vW[(h * Cn + c) * Cn + d]; bv = vb[h * Cn + d]; }
    g_WT2[c * WCOLS + j] = w;
    if (c == 0) g_bT[j] = bv;
}

// ---------------- grid barrier ----------------
__device__ __forceinline__ void gsync(unsigned gen) {
    __threadfence();
    __syncthreads();
    if (threadIdx.x == 0) {
        unsigned arrived = atomicAdd(&g_bar_cnt, 1u) + 1u;
        if (arrived == NCTA * gen) {
            g_bar_gen = gen;
        } else {
            while (g_bar_gen < gen) { }
        }
    }
    __syncthreads();
}

// ---------------- persistent main kernel ----------------
// smem layout (floats):
//   [0, 45408)            sWT  : qkv weights, resident all 64 steps
//   [45408, 46432)        qsm  : Q tile of this CTA (phase A -> phase B)
//   [46432, 46432+8544)   scr  : per-phase scratch
#define SWT_F   (Cn * WCOLS)          // 45408
#define QS_F    1024
#define SCR_F   8544
#define SMEM_B  ((SWT_F + QS_F + SCR_F) * 4)   // 219904 bytes

__global__ void __launch_bounds__(256, 1) k_main(const float* __restrict__ obs,
                                                 const float* __restrict__ maskp,
                                                 const float* __restrict__ rarW,
                                                 const int* __restrict__ lengths,
                                                 float* __restrict__ out) {
    extern __shared__ float sm[];
    float* sWT = sm;
    float* qsm = sm + SWT_F;
    float* scr = sm + SWT_F + QS_F;

    int tid = threadIdx.x;
    int cid = blockIdx.x;
    int b = cid & 31, chunk = cid >> 5, n0 = chunk * 32;

    // load qkv weights into smem once
    for (int i = tid; i < SWT_F; i += 256) sWT[i] = g_WT2[i];
    __syncthreads();

    unsigned gen = 0;

    for (int t = 0; t < Tn; t++) {
        // ---------------- Phase A: qkv projection ----------------
        {
            float* comb = scr;   // 32*132
            for (int idx = tid; idx < 32 * CP; idx += 256) {
                int rr = idx / CP, c = idx - rr * CP;
                int n = n0 + rr;
                float v = 0.0f;
                if (c < Dn)       v = obs[(((size_t)b * Tn + t) * Nn + n) * Dn + c];
                else if (c == Dn) v = g_rar[(b * Tn + t) * Nn + n];
                else if (c < Cn)  v = __ldcg(&g_h[((size_t)b * Nn + n) * Dn + (c - Dn - 1)]);
                comb[idx] = v;
            }
            __syncthreads();

            int rr = tid >> 3, c8 = tid & 7;
            float4 acc[11];
            #pragma unroll
            for (int j = 0; j < 11; j++) acc[j] = make_float4(0, 0, 0, 0);
            const float4* W4 = (const float4*)sWT;
            const float* zrow = comb + rr * CP;
            for (int c = 0; c < Cn; c++) {
                float z = zrow[c];
                const float4* wr = W4 + c * (WCOLS / 4) + c8;
                #pragma unroll
                for (int j = 0; j < 11; j++) {
                    float4 w = wr[8 * j];
                    acc[j].x += z * w.x; acc[j].y += z * w.y;
                    acc[j].z += z * w.z; acc[j].w += z * w.w;
                }
            }
            int n = n0 + rr;
            #pragma unroll
            for (int j = 0; j < 11; j++) {
                float vv[4] = { acc[j].x, acc[j].y, acc[j].z, acc[j].w };
                #pragma unroll
                for (int e = 0; e < 4; e++) {
                    int col = (c8 + 8 * j) * 4 + e;
                    float val = vv[e] + g_bT[col];
                    if (col < 32) {
                        qsm[rr * 32 + col] = val;
                    } else if (col < 64) {
                        int jj = col - 32;
                        __stcg(&g_K[(((size_t)b * 2 + (jj >> 4)) * Nn + n) * CKn + (jj & 15)], val);
                    } else if (col < 322) {
                        int jj = col - 64;
                        int h = jj >= Cn;
                        int d = jj - h * Cn;
                        __stcg(&g_V[(((size_t)b * 2 + h) * Nn + n) * CP + d], val);
                    }
                }
            }
        }
        gsync(++gen);

        // ---------------- Phase B: attention ----------------
        {
            float* Ks  = scr;                    // 128*20
            float* Ss  = scr + 2560;             // 32*132
            float* rs  = scr + 6784;             // 128
            float* msv = rs + 128;               // 128
            unsigned char* mskb = (unsigned char*)(msv + 128);  // 32*128 bytes

            if (tid < 128) {
                rs[tid]  = g_rar[(b * Tn + t) * Nn + tid];
                msv[tid] = maskp[((size_t)b * Tn + t) * Nn + tid];
            }
            __syncthreads();
            for (int idx = tid; idx < 32 * 128; idx += 256) {
                int rr2 = idx >> 7, m = idx & 127;
                int n = n0 + rr2;
                unsigned char km = 0;
                if (n != m) {
                    float am  = msv[n] * msv[m];
                    float rm  = -rarW[n * Nn + m] * fabsf(rs[n] - rs[m]);
                    float val = g_adj[n * Nn + m] * (1.0f + rm) * am;
                    km = (val == 0.0f) ? 1 : 0;
                }
                mskb[idx] = km;
            }

            int r  = tid >> 3, c8 = tid & 7;
            int rg = tid >> 5, cc = tid & 31;
            float4 o0 = make_float4(0,0,0,0), o1 = o0, o2 = o0, o3 = o0;
            float e0 = 0.f, e1 = 0.f, e2 = 0.f, e3 = 0.f;

            for (int h = 0; h < 2; h++) {
                __syncthreads();
                const float4* gk4 = (const float4*)(g_K + ((size_t)(b * 2 + h) * Nn) * CKn);
                for (int idx = tid; idx < 512; idx += 256) {
                    int m = idx >> 2, kq = idx & 3;
                    float4 kv = __ldcg(&gk4[m * 4 + kq]);
                    *(float4*)(Ks + m * 20 + kq * 4) = kv;
                }
                __syncthreads();

                float4 q4[4];
                const float4* qrow = (const float4*)(qsm + r * 32 + h * 16);
                q4[0] = qrow[0]; q4[1] = qrow[1]; q4[2] = qrow[2]; q4[3] = qrow[3];

                float sv[16]; float mx = -3.0e38f;
                #pragma unroll
                for (int jm = 0; jm < 16; jm++) {
                    int m = c8 + 8 * jm;
                    const float4* kr = (const float4*)(Ks + m * 20);
                    float d = 0.0f;
                    #pragma unroll
                    for (int kq = 0; kq < 4; kq++) {
                        float4 kv = kr[kq];
                        d += q4[kq].x * kv.x + q4[kq].y * kv.y + q4[kq].z * kv.z + q4[kq].w * kv.w;
                    }
                    d *= 0.25f;
                    d = d > 0.0f ? d : 0.2f * d;
                    if (mskb[(r << 7) + m]) d = NEGV;
                    sv[jm] = d;
                    mx = fmaxf(mx, d);
                }
                #pragma unroll
                for (int o = 1; o < 8; o <<= 1) mx = fmaxf(mx, __shfl_xor_sync(0xffffffffu, mx, o));
                float sum = 0.0f;
                #pragma unroll
                for (int jm = 0; jm < 16; jm++) { float ee = __expf(sv[jm] - mx); sv[jm] = ee; sum += ee; }
                #pragma unroll
                for (int o = 1; o < 8; o <<= 1) sum += __shfl_xor_sync(0xffffffffu, sum, o);
                float inv = 1.0f / sum;
                #pragma unroll
                for (int jm = 0; jm < 16; jm++) Ss[r * CP + c8 + 8 * jm] = sv[jm] * inv;
                __syncthreads();

                const float4* Ss4 = (const float4*)Ss;
                const float*  Vb  = g_V + ((size_t)(b * 2 + h) * Nn) * CP;
                const float4* Vb4 = (const float4*)Vb;
                for (int m4 = 0; m4 < 32; m4++) {
                    float4 pr0 = Ss4[(rg * 4 + 0) * 33 + m4];
                    float4 pr1 = Ss4[(rg * 4 + 1) * 33 + m4];
                    float4 pr2 = Ss4[(rg * 4 + 2) * 33 + m4];
                    float4 pr3 = Ss4[(rg * 4 + 3) * 33 + m4];
                    #pragma unroll
                    for (int i = 0; i < 4; i++) {
                        int m = m4 * 4 + i;
                        float4 v = __ldcg(&Vb4[m * 33 + cc]);
                        float p0 = (i == 0) ? pr0.x : (i == 1) ? pr0.y : (i == 2) ? pr0.z : pr0.w;
                        float p1 = (i == 0) ? pr1.x : (i == 1) ? pr1.y : (i == 2) ? pr1.z : pr1.w;
                        float p2 = (i == 0) ? pr2.x : (i == 1) ? pr2.y : (i == 2) ? pr2.z : pr2.w;
                        float p3 = (i == 0) ? pr3.x : (i == 1) ? pr3.y : (i == 2) ? pr3.z : pr3.w;
                        o0.x += p0 * v.x; o0.y += p0 * v.y; o0.z += p0 * v.z; o0.w += p0 * v.w;
                        o1.x += p1 * v.x; o1.y += p1 * v.y; o1.z += p1 * v.z; o1.w += p1 * v.w;
                        o2.x += p2 * v.x; o2.y += p2 * v.y; o2.z += p2 * v.z; o2.w += p2 * v.w;
                        o3.x += p3 * v.x; o3.y += p3 * v.y; o3.z += p3 * v.z; o3.w += p3 * v.w;
                        if (cc == 0) {
                            float vl = __ldcg(&Vb[m * CP + 128]);
                            e0 += p0 * vl; e1 += p1 * vl; e2 += p2 * vl; e3 += p3 * vl;
                        }
                    }
                }
            }
            float4 oo[4] = { o0, o1, o2, o3 };
            float  ee[4] = { e0, e1, e2, e3 };
            #pragma unroll
            for (int i = 0; i < 4; i++) {
                int n = n0 + rg * 4 + i;
                float4 a = oo[i];
                a.x *= 0.5f; a.y *= 0.5f; a.z *= 0.5f; a.w *= 0.5f;
                __stcg((float4*)(g_att + ((size_t)b * Nn + n) * CP) + cc, a);
                if (cc == 0) __stcg(&g_att[((size_t)b * Nn + n) * CP + 128], ee[i] * 0.5f);
            }
        }
        gsync(++gen);

        // ---------------- Phase C: gates (CTA = node) ----------------
        {
            int n = cid;
            float* zs  = scr;             // 32*132
            float* h1s = scr + 4224;      // 32*64
            float* us  = h1s + 2048;      // 32*64
            float* gb  = us + 2048;       // 192
            float* msk = gb + 192;        // 32

            const float4* att4 = (const float4*)g_att;
            for (int idx = tid; idx < 32 * 33; idx += 256) {
                int b2 = idx / 33, q = idx - b2 * 33;
                ((float4*)zs)[idx] = __ldcg(&att4[((size_t)b2 * Nn + n) * 33 + q]);
            }
            if (tid < G3) gb[tid] = g_gB[n * G3 + tid];
            if (tid < 32) msk[tid] = maskp[((size_t)tid * Tn + t) * Nn + n];
            __syncthreads();

            int bb = tid >> 3, c8 = tid & 7;
            bool ob = msk[bb] > 0.0f;
            const float4* gw4 = (const float4*)(g_gW + (size_t)n * Cn * G3);

            float4 a[4];
            #pragma unroll
            for (int j = 0; j < 4; j++) a[j] = make_float4(0, 0, 0, 0);
            for (int c = 0; c < Cn; c++) {
                float z = zs[bb * CP + c];
                const float4* wr = gw4 + c * (G3 / 4) + c8;
                #pragma unroll
                for (int j = 0; j < 4; j++) {
                    float4 w = __ldg(&wr[8 * j]);
                    a[j].x += z * w.x; a[j].y += z * w.y; a[j].z += z * w.z; a[j].w += z * w.w;
                }
            }
            #pragma unroll
            for (int j = 0; j < 4; j++) {
                float vv[4] = { a[j].x, a[j].y, a[j].z, a[j].w };
                #pragma unroll
                for (int e = 0; e < 4; e++) {
                    int o = (c8 + 8 * j) * 4 + e;
                    float g = 1.0f / (1.0f + __expf(-(vv[e] + gb[o])));
                    if (o < 64) {
                        float hv = __ldcg(&g_h[((size_t)bb * Nn + n) * Dn + o]);
                        h1s[bb * 64 + o] = ob ? g * hv : hv;
                    } else {
                        us[bb * 64 + (o - 64)] = g;
                    }
                }
            }
            __syncthreads();

            for (int idx = tid; idx < 32 * CP; idx += 256) {
                int b2 = idx / CP, c = idx - b2 * CP;
                float v = 0.0f;
                if (c < Dn)       v = obs[(((size_t)b2 * Tn + t) * Nn + n) * Dn + c];
                else if (c == Dn) v = g_rar[(b2 * Tn + t) * Nn + n];
                else if (c < Cn)  v = h1s[b2 * 64 + (c - Dn - 1)];
                zs[idx] = v;
            }
            __syncthreads();

            float4 a2[2];
            a2[0] = make_float4(0, 0, 0, 0); a2[1] = a2[0];
            for (int c = 0; c < Cn; c++) {
                float z = zs[bb * CP + c];
                const float4* wr = gw4 + c * (G3 / 4) + 32 + c8;
                #pragma unroll
                for (int j = 0; j < 2; j++) {
                    float4 w = __ldg(&wr[8 * j]);
                    a2[j].x += z * w.x; a2[j].y += z * w.y; a2[j].z += z * w.z; a2[j].w += z * w.w;
                }
            }
            bool fin = (t == lengths[bb] - 1);
            #pragma unroll
            for (int j = 0; j < 2; j++) {
                float vv[4] = { a2[j].x, a2[j].y, a2[j].z, a2[j].w };
                #pragma unroll
                for (int e = 0; e < 4; e++) {
                    int d = (c8 + 8 * j) * 4 + e;
                    float cand = tanhf(vv[e] + gb[128 + d]);
                    float h1 = h1s[bb * 64 + d];
                    float u  = us[bb * 64 + d];
                    float h2 = ob ? (1.0f - u) * h1 + u * cand : h1;
                    __stcg(&g_h[((size_t)bb * Nn + n) * Dn + d], h2);
                    if (fin) out[((size_t)bb * Nn + n) * Dn + d] = h2;
                }
            }
        }
        gsync(++gen);
    }
}

// ---------------- launcher ----------------
extern "C" void kernel_launch(void* const* d_in, const int* in_sizes, int n_in,
                              void* d_out, int out_size) {
    (void)n_in; (void)out_size;
    const float* obs   = (const float*)d_in[0];
    const float* maskp = (const float*)d_in[1];
    const float* avg   = (const float*)d_in[2];
    const float* plm   = (const float*)d_in[3];
    const int* lengths;
    int off;
    if (in_sizes[4] == Bn) { lengths = (const int*)d_in[4];  off = 5; }
    else                   { lengths = (const int*)d_in[25]; off = 4; }
    const float* rarW  = (const float*)d_in[off + 0];
    const float* pfW1  = (const float*)d_in[off + 1];
    const float* pfb1  = (const float*)d_in[off + 2];
    const float* pfW2  = (const float*)d_in[off + 3];
    const float* pfb2  = (const float*)d_in[off + 4];
    const float* pgW1  = (const float*)d_in[off + 5];
    const float* pgb1  = (const float*)d_in[off + 6];
    const float* pgW2  = (const float*)d_in[off + 7];
    const float* pgb2  = (const float*)d_in[off + 8];
    const float* rstW  = (const float*)d_in[off + 9];
    const float* rstB  = (const float*)d_in[off + 10];
    const float* updW  = (const float*)d_in[off + 11];
    const float* updB  = (const float*)d_in[off + 12];
    const float* candW = (const float*)d_in[off + 13];
    const float* candB = (const float*)d_in[off + 14];
    const float* qW    = (const float*)d_in[off + 15];
    const float* qb    = (const float*)d_in[off + 16];
    const float* kW    = (const float*)d_in[off + 17];
    const float* kb    = (const float*)d_in[off + 18];
    const float* vW    = (const float*)d_in[off + 19];
    const float* vb    = (const float*)d_in[off + 20];
    float* out = (float*)d_out;

    static int configured = 0;
    if (!configured) {
        cudaFuncSetAttribute(k_main, cudaFuncAttributeMaxDynamicSharedMemorySize, SMEM_B);
        configured = 1;
    }

    k_reset<<<(Bn * Nn * Dn + 255) / 256, 256>>>();
    k_pre0<<<Bn, Nn>>>(maskp, avg);
    k_pre1<<<Nn, 128>>>(plm, pfW1, pfb1, pfW2, pfb2, pgW1, pgb1, pgW2, pgb2);
    k_pre2<<<Nn, Nn>>>();
    k_pre3<<<Nn, 256>>>(rstW, rstB, updW, updB, candW, candB);
    k_pre4<<<Cn, WCOLS>>>(qW, qb, kW, kb, vW, vb);

    k_main<<<NCTA, 256, SMEM_B>>>(obs, maskp, rarW, lengths, out);
}

// round 7
// speedup vs baseline: 1.8799x; 1.3971x over previous
#include <cuda_runtime.h>
#include <cstdint>

#define Bn   32
#define Tn   64
#define Nn   128
#define Dn   64
#define Cn   129
#define CP   132
#define CKn  16
#define QDn  5
#define NEn  8
#define PLMn 768
#define G3   192
#define NEGV (-9e15f)

#define WCOLS 352          // 322 qkv outputs padded (88 float4 chunks)
#define NCTA  128u

// ---------------- device scratch ----------------
__device__ __align__(16) float g_qv[Nn * QDn];
__device__ __align__(16) float g_ne[Nn * NEn];
__device__ __align__(16) float g_adj[Nn * Nn];
__device__ __align__(16) float g_rar[Bn * Tn * Nn];
__device__ __align__(16) float g_gW[Nn * Cn * G3];
__device__ __align__(16) float g_gB[Nn * G3];
__device__ __align__(16) float g_WT2[Cn * WCOLS];
__device__ __align__(16) float g_bT[WCOLS];
__device__ __align__(16) float g_h[Bn * Nn * Dn];
__device__ __align__(16) float g_K[Bn * 2 * Nn * CKn];
__device__ __align__(16) float g_V[Bn * 2 * Nn * CP];
__device__ __align__(16) float g_att[Bn * Nn * CP];

__device__ unsigned g_ctrB1[32];   // A->B   per-batch (4 CTAs)
__device__ unsigned g_ctrC1[4];    // B->C   per-chunk (32 CTAs)
__device__ unsigned g_ctrC2[4];    // C->A   per-chunk
__device__ unsigned g_ctrB2[32];   // C->A   per-batch

// ---------------- f32x2 helpers ----------------
#define FMA2(acc, w, z) asm("fma.rn.f32x2 %0, %1, %2, %0;" : "+l"(acc) : "l"(w), "l"(z))

__device__ __forceinline__ unsigned long long pk2(float z) {
    unsigned long long r;
    asm("mov.b64 %0, {%1, %1};" : "=l"(r) : "f"(z));
    return r;
}
__device__ __forceinline__ float2 up2(unsigned long long v) {
    float2 r;
    asm("mov.b64 {%0, %1}, %2;" : "=f"(r.x), "=f"(r.y) : "l"(v));
    return r;
}

// ---------------- precompute ----------------
__global__ void k_pre0(const float* __restrict__ maskp, const float* __restrict__ avg) {
    int b = blockIdx.x, n = threadIdx.x;
    int gtid = b * 128 + n;
    for (int i = gtid; i < Bn * Nn * Dn; i += 4096) g_h[i] = 0.0f;
    if (gtid < 32) { g_ctrB1[gtid] = 0; g_ctrB2[gtid] = 0; }
    if (gtid < 4)  { g_ctrC1[gtid] = 0; g_ctrC2[gtid] = 0; }
    float s = 0.0f;
    for (int t = 0; t < Tn; t++) s += maskp[(b * Tn + t) * Nn + n];
    float inv = 1.0f / (s + 1.0f);
    for (int t = 0; t < Tn; t++)
        g_rar[(b * Tn + t) * Nn + n] = 0.5f * tanhf(avg[(b * Tn + t) * Nn + n] * inv);
}

__global__ void k_pre1(const float* __restrict__ plm,
                       const float* __restrict__ pfW1, const float* __restrict__ pfb1,
                       const float* __restrict__ pfW2, const float* __restrict__ pfb2,
                       const float* __restrict__ pgW1, const float* __restrict__ pgb1,
                       const float* __restrict__ pgW2, const float* __restrict__ pgb2) {
    int n = blockIdx.x, j = threadIdx.x;
    __shared__ float h1[128], h2[128];
    __shared__ float nrm;
    const float* p = plm + (size_t)n * PLMn;
    float a = 0.0f, bv = 0.0f;
    for (int c = 0; c < PLMn; c++) {
        float pv = p[c];
        a  += pv * pfW1[c * 128 + j];
        bv += pv * pgW1[c * 128 + j];
    }
    a += pfb1[j]; bv += pgb1[j];
    h1[j] = a  > 0.0f ? a  : 0.0f;
    h2[j] = bv > 0.0f ? bv : 0.0f;
    __syncthreads();
    if (j < QDn) {
        float s = pfb2[j];
        for (int c = 0; c < 128; c++) s += h1[c] * pfW2[c * QDn + j];
        g_qv[n * QDn + j] = s;
    }
    if (j < NEn) {
        float s = pgb2[j];
        for (int c = 0; c < 128; c++) s += h2[c] * pgW2[c * NEn + j];
        g_ne[n * NEn + j] = s;
    }
    __syncthreads();
    if (j == 0) {
        float s = 0.0f;
        for (int e = 0; e < NEn; e++) { float v = g_ne[n * NEn + e]; s += v * v; }
        nrm = fmaxf(sqrtf(s), 1e-12f);
    }
    __syncthreads();
    if (j < NEn) g_ne[n * NEn + j] /= nrm;
}

__global__ void k_pre2() {
    int n = blockIdx.x, m = threadIdx.x;
    __shared__ float red[128];
    float s = 0.0f;
    for (int e = 0; e < NEn; e++) s += g_ne[n * NEn + e] * g_ne[m * NEn + e];
    red[m] = s;
    __syncthreads();
    for (int st = 64; st > 0; st >>= 1) { if (m < st) red[m] = fmaxf(red[m], red[m + st]); __syncthreads(); }
    float mx = red[0];
    __syncthreads();
    float e = expf(s - mx);
    red[m] = e;
    __syncthreads();
    for (int st = 64; st > 0; st >>= 1) { if (m < st) red[m] += red[m + st]; __syncthreads(); }
    g_adj[n * Nn + m] = e / red[0];
}

__global__ void k_pre3(const float* __restrict__ rstW, const float* __restrict__ rstB,
                       const float* __restrict__ updW, const float* __restrict__ updB,
                       const float* __restrict__ candW, const float* __restrict__ candB) {
    int n = blockIdx.x;
    __shared__ float qv[QDn];
    if (threadIdx.x < QDn) qv[threadIdx.x] = g_qv[n * QDn + threadIdx.x];
    __syncthreads();
    for (int idx = threadIdx.x; idx < Cn * Dn; idx += blockDim.x) {
        int c = idx / Dn, o = idx % Dn;
        float r = 0.0f, u = 0.0f, cd = 0.0f;
        for (int q = 0; q < QDn; q++) {
            float s = qv[q];
            int off = (q * Cn + c) * Dn + o;
            r  += s * rstW[off];
            u  += s * updW[off];
            cd += s * candW[off];
        }
        float* dst = g_gW + ((size_t)n * Cn + c) * G3;
        dst[o] = r; dst[64 + o] = u; dst[128 + o] = cd;
    }
    for (int o = threadIdx.x; o < Dn; o += blockDim.x) {
        float r = 0.0f, u = 0.0f, cd = 0.0f;
        for (int q = 0; q < QDn; q++) {
            float s = qv[q];
            r  += s * rstB[q * Dn + o];
            u  += s * updB[q * Dn + o];
            cd += s * candB[q * Dn + o];
        }
        g_gB[n * G3 + o] = r; g_gB[n * G3 + 64 + o] = u; g_gB[n * G3 + 128 + o] = cd;
    }
}

__global__ void k_pre4(const float* __restrict__ qW, const float* __restrict__ qb,
                       const float* __restrict__ kW, const float* __restrict__ kb,
                       const float* __restrict__ vW, const float* __restrict__ vb) {
    int c = blockIdx.x;       // 0..128
    int j = threadIdx.x;      // 0..351
    float w = 0.0f, bv = 0.0f;
    if (j < 32)       { int h = j >> 4, kk = j & 15;                    w = qW[(h * Cn + c) * CKn + kk]; bv = qb[h * CKn + kk]; }
    else if (j < 64)  { int jj = j - 32; int h = jj >> 4, kk = jj & 15; w = kW[(h * Cn + c) * CKn + kk]; bv = kb[h * CKn + kk]; }
    else if (j < 322) { int jj = j - 64; int h = jj >= Cn; int d = jj - h * Cn; w = vW[(h * Cn + c) * Cn + d]; bv = vb[h * Cn + d]; }
    g_WT2[c * WCOLS + j] = w;
    if (c == 0) g_bT[j] = bv;
}

// ---------------- group barrier ----------------
__device__ __forceinline__ void gsync(unsigned* ctr, unsigned target) {
    __syncthreads();
    if (threadIdx.x == 0) {
        __threadfence();
        atomicAdd(ctr, 1u);
        while (*(volatile unsigned*)ctr < target) { }
        __threadfence();
    }
    __syncthreads();
}

// ---------------- persistent main kernel ----------------
// smem floats: [0,45408) W region (A: qkv weights / B: V tile / C: gate weights)
//              [45408,45760) bias   [45760,46784) qsm   [46784,55328) scratch
#define SWT_F   (Cn * WCOLS)          // 45408
#define BIAS_F  352
#define QS_F    1024
#define SCR_F   8544
#define SMEM_B  ((SWT_F + BIAS_F + QS_F + SCR_F) * 4)   // 221312 bytes

__global__ void __launch_bounds__(256, 1) k_main(const float* __restrict__ obs,
                                                 const float* __restrict__ maskp,
                                                 const float* __restrict__ rarW,
                                                 const int* __restrict__ lengths,
                                                 float* __restrict__ out) {
    extern __shared__ float sm[];
    float* sW    = sm;
    float* sBias = sm + SWT_F;
    float* qsm   = sBias + BIAS_F;
    float* scr   = qsm + QS_F;

    int tid = threadIdx.x;
    int cid = blockIdx.x;
    int b = cid & 31, chunk = cid >> 5, n0 = chunk * 32;

    // persistent bias: grid-stride so ALL 352 entries are written (round-5 bug fix)
    for (int i = tid; i < BIAS_F; i += 256) sBias[i] = g_bT[i];
    // (read only after the phase-A __syncthreads each step)

    for (int t = 0; t < Tn; t++) {
        // ================= Phase A: qkv projection =================
        {
            // stage weights (181.6KB) into smem
            const float4* wsrc = (const float4*)g_WT2;
            float4* wdst = (float4*)sW;
            for (int i = tid; i < SWT_F / 4; i += 256) wdst[i] = wsrc[i];

            float* comb = scr;   // 32 x 132
            for (int idx = tid; idx < 32 * CP; idx += 256) {
                int rr = idx / CP, c = idx - rr * CP;
                int n = n0 + rr;
                float v = 0.0f;
                if (c < Dn)       v = obs[(((size_t)b * Tn + t) * Nn + n) * Dn + c];
                else if (c == Dn) v = g_rar[(b * Tn + t) * Nn + n];
                else if (c < Cn)  v = __ldcg(&g_h[((size_t)b * Nn + n) * Dn + (c - Dn - 1)]);
                comb[idx] = v;
            }
            __syncthreads();

            int rg = tid >> 5, tc = tid & 31;
            bool has3 = (tc < 24);
            unsigned long long acc[4][3][2];
            #pragma unroll
            for (int i = 0; i < 4; i++)
                #pragma unroll
                for (int j = 0; j < 3; j++) { acc[i][j][0] = 0ull; acc[i][j][1] = 0ull; }

            const float* zrow = comb + rg * 4 * CP;
            ulonglong2 wz; wz.x = 0ull; wz.y = 0ull;
            #pragma unroll 3
            for (int c = 0; c < Cn; c++) {
                const ulonglong2* wp = (const ulonglong2*)(sW + c * WCOLS);
                ulonglong2 w0 = wp[tc];
                ulonglong2 w1 = wp[tc + 32];
                ulonglong2 w2 = has3 ? wp[tc + 64] : wz;
                #pragma unroll
                for (int i = 0; i < 4; i++) {
                    unsigned long long z2 = pk2(zrow[i * CP + c]);
                    FMA2(acc[i][0][0], w0.x, z2); FMA2(acc[i][0][1], w0.y, z2);
                    FMA2(acc[i][1][0], w1.x, z2); FMA2(acc[i][1][1], w1.y, z2);
                    FMA2(acc[i][2][0], w2.x, z2); FMA2(acc[i][2][1], w2.y, z2);
                }
            }

            #pragma unroll
            for (int i = 0; i < 4; i++) {
                int rr = rg * 4 + i, n = n0 + rr;
                #pragma unroll
                for (int j = 0; j < 3; j++) {
                    if (j == 2 && !has3) break;
                    int chnk = tc + 32 * j;
                    float2 lo = up2(acc[i][j][0]), hi = up2(acc[i][j][1]);
                    float vals[4] = { lo.x, lo.y, hi.x, hi.y };
                    #pragma unroll
                    for (int e = 0; e < 4; e++) {
                        int col = chnk * 4 + e;
                        if (col >= 322) continue;
                        float val = vals[e] + sBias[col];
                        if (col < 32) {
                            qsm[rr * 32 + col] = val;
                        } else if (col < 64) {
                            int jj = col - 32;
                            __stcg(&g_K[((b * 2 + (jj >> 4)) * Nn + n) * CKn + (jj & 15)], val);
                        } else {
                            int jj = col - 64;
                            int hh = jj >= Cn;
                            int d = jj - hh * Cn;
                            __stcg(&g_V[(((size_t)b * 2 + hh) * Nn + n) * CP + d], val);
                        }
                    }
                }
            }
        }
        gsync(&g_ctrB1[b], 4u * (t + 1));

        // ================= Phase B: attention =================
        {
            float* Vs  = sW;                     // 2*128*132 = 33792 floats
            float* Ks  = scr;                    // 128*20
            float* Ss  = scr + 2560;             // 32*132
            float* rs  = scr + 6784;             // 128
            float* msv = rs + 128;               // 128
            unsigned char* mskb = (unsigned char*)(msv + 128);  // 32*128 bytes

            // stage V (both heads) into smem
            {
                const float4* vsrc = (const float4*)(g_V + (size_t)(b * 2) * Nn * CP);
                float4* vdst = (float4*)Vs;
                for (int i = tid; i < 2 * Nn * CP / 4; i += 256) vdst[i] = __ldcg(&vsrc[i]);
            }
            if (tid < 128) {
                rs[tid]  = g_rar[(b * Tn + t) * Nn + tid];
                msv[tid] = maskp[((size_t)b * Tn + t) * Nn + tid];
            }
            __syncthreads();
            for (int idx = tid; idx < 32 * 128; idx += 256) {
                int rr2 = idx >> 7, m = idx & 127;
                int n = n0 + rr2;
                unsigned char km = 0;
                if (n != m) {
                    float am  = msv[n] * msv[m];
                    float rm  = -rarW[n * Nn + m] * fabsf(rs[n] - rs[m]);
                    float val = g_adj[n * Nn + m] * (1.0f + rm) * am;
                    km = (val == 0.0f) ? 1 : 0;
                }
                mskb[idx] = km;
            }

            int r  = tid >> 3, c8 = tid & 7;
            int rg = tid >> 5, cc = tid & 31;
            unsigned long long o[4][2];
            #pragma unroll
            for (int i = 0; i < 4; i++) { o[i][0] = 0ull; o[i][1] = 0ull; }
            float ex[4] = { 0.f, 0.f, 0.f, 0.f };

            for (int h = 0; h < 2; h++) {
                __syncthreads();
                const float4* gk4 = (const float4*)(g_K + ((size_t)(b * 2 + h) * Nn) * CKn);
                for (int idx = tid; idx < 512; idx += 256) {
                    int m = idx >> 2, kq = idx & 3;
                    float4 kv = __ldcg(&gk4[m * 4 + kq]);
                    *(float4*)(Ks + m * 20 + kq * 4) = kv;
                }
                __syncthreads();

                float4 q4[4];
                const float4* qrow = (const float4*)(qsm + r * 32 + h * 16);
                q4[0] = qrow[0]; q4[1] = qrow[1]; q4[2] = qrow[2]; q4[3] = qrow[3];

                float sv[16]; float mx = -3.0e38f;
                #pragma unroll
                for (int jm = 0; jm < 16; jm++) {
                    int m = c8 + 8 * jm;
                    const float4* kr = (const float4*)(Ks + m * 20);
                    float d = 0.0f;
                    #pragma unroll
                    for (int kq = 0; kq < 4; kq++) {
                        float4 kv = kr[kq];
                        d += q4[kq].x * kv.x + q4[kq].y * kv.y + q4[kq].z * kv.z + q4[kq].w * kv.w;
                    }
                    d *= 0.25f;
                    d = d > 0.0f ? d : 0.2f * d;
                    if (mskb[(r << 7) + m]) d = NEGV;
                    sv[jm] = d;
                    mx = fmaxf(mx, d);
                }
                #pragma unroll
                for (int oo = 1; oo < 8; oo <<= 1) mx = fmaxf(mx, __shfl_xor_sync(0xffffffffu, mx, oo));
                float sum = 0.0f;
                #pragma unroll
                for (int jm = 0; jm < 16; jm++) { float ee = __expf(sv[jm] - mx); sv[jm] = ee; sum += ee; }
                #pragma unroll
                for (int oo = 1; oo < 8; oo <<= 1) sum += __shfl_xor_sync(0xffffffffu, sum, oo);
                float inv = 1.0f / sum;
                #pragma unroll
                for (int jm = 0; jm < 16; jm++) Ss[r * CP + c8 + 8 * jm] = sv[jm] * inv;
                __syncthreads();

                const float4* Ss4 = (const float4*)Ss;
                const float* Vh = Vs + (size_t)h * Nn * CP;
                for (int m4 = 0; m4 < 32; m4++) {
                    float4 pr[4];
                    #pragma unroll
                    for (int i = 0; i < 4; i++) pr[i] = Ss4[(rg * 4 + i) * 33 + m4];
                    #pragma unroll
                    for (int i2 = 0; i2 < 4; i2++) {
                        int m = m4 * 4 + i2;
                        ulonglong2 v = *(const ulonglong2*)(Vh + m * CP + cc * 4);
                        float p0 = (i2 == 0) ? pr[0].x : (i2 == 1) ? pr[0].y : (i2 == 2) ? pr[0].z : pr[0].w;
                        float p1 = (i2 == 0) ? pr[1].x : (i2 == 1) ? pr[1].y : (i2 == 2) ? pr[1].z : pr[1].w;
                        float p2 = (i2 == 0) ? pr[2].x : (i2 == 1) ? pr[2].y : (i2 == 2) ? pr[2].z : pr[2].w;
                        float p3 = (i2 == 0) ? pr[3].x : (i2 == 1) ? pr[3].y : (i2 == 2) ? pr[3].z : pr[3].w;
                        unsigned long long z0 = pk2(p0), z1 = pk2(p1), z2 = pk2(p2), z3 = pk2(p3);
                        FMA2(o[0][0], v.x, z0); FMA2(o[0][1], v.y, z0);
                        FMA2(o[1][0], v.x, z1); FMA2(o[1][1], v.y, z1);
                        FMA2(o[2][0], v.x, z2); FMA2(o[2][1], v.y, z2);
                        FMA2(o[3][0], v.x, z3); FMA2(o[3][1], v.y, z3);
                        if (cc == 0) {
                            float vl = Vh[m * CP + 128];
                            ex[0] += p0 * vl; ex[1] += p1 * vl; ex[2] += p2 * vl; ex[3] += p3 * vl;
                        }
                    }
                }
            }
            #pragma unroll
            for (int i = 0; i < 4; i++) {
                int n = n0 + rg * 4 + i;
                float2 x0 = up2(o[i][0]), x1 = up2(o[i][1]);
                float4 a = make_float4(x0.x * 0.5f, x0.y * 0.5f, x1.x * 0.5f, x1.y * 0.5f);
                __stcg((float4*)(g_att + ((size_t)b * Nn + n) * CP) + cc, a);
                if (cc == 0) __stcg(&g_att[((size_t)b * Nn + n) * CP + 128], ex[i] * 0.5f);
            }
        }
        gsync(&g_ctrC1[chunk], 32u * (t + 1));

        // ================= Phase C: gates (CTA = node) =================
        {
            int n = cid;
            float* gWs = sW;              // 129*192 = 24768 floats
            float* zs  = scr;             // 32*132
            float* h1s = scr + 4224;      // 32*64
            float* us  = h1s + 2048;      // 32*64
            float* gb  = us + 2048;       // 192
            float* msk = gb + 192;        // 32

            {
                const float4* wsrc = (const float4*)(g_gW + (size_t)n * Cn * G3);
                float4* wdst = (float4*)gWs;
                for (int i = tid; i < Cn * G3 / 4; i += 256) wdst[i] = __ldg(&wsrc[i]);
            }
            const float4* att4 = (const float4*)g_att;
            for (int idx = tid; idx < 32 * 33; idx += 256) {
                int b2 = idx / 33, q = idx - b2 * 33;
                ((float4*)zs)[idx] = __ldcg(&att4[((size_t)b2 * Nn + n) * 33 + q]);
            }
            if (tid < G3) gb[tid] = g_gB[n * G3 + tid];
            if (tid < 32) msk[tid] = maskp[((size_t)tid * Tn + t) * Nn + n];
            __syncthreads();

            int bb = tid >> 3, c8 = tid & 7;
            bool ob = msk[bb] > 0.0f;

            unsigned long long a1[4][2];
            #pragma unroll
            for (int j = 0; j < 4; j++) { a1[j][0] = 0ull; a1[j][1] = 0ull; }
            for (int c = 0; c < Cn; c++) {
                unsigned long long z2 = pk2(zs[bb * CP + c]);
                const ulonglong2* wp = (const ulonglong2*)(gWs + c * G3);
                #pragma unroll
                for (int j = 0; j < 4; j++) {
                    ulonglong2 w = wp[c8 + 8 * j];
                    FMA2(a1[j][0], w.x, z2); FMA2(a1[j][1], w.y, z2);
                }
            }
            #pragma unroll
            for (int j = 0; j < 4; j++) {
                float2 lo = up2(a1[j][0]), hi = up2(a1[j][1]);
                float vv[4] = { lo.x, lo.y, hi.x, hi.y };
                #pragma unroll
                for (int e = 0; e < 4; e++) {
                    int o = (c8 + 8 * j) * 4 + e;
                    float g = 1.0f / (1.0f + __expf(-(vv[e] + gb[o])));
                    if (o < 64) {
                        float hv = __ldcg(&g_h[((size_t)bb * Nn + n) * Dn + o]);
                        h1s[bb * 64 + o] = ob ? g * hv : hv;
                    } else {
                        us[bb * 64 + (o - 64)] = g;
                    }
                }
            }
            __syncthreads();

            for (int idx = tid; idx < 32 * CP; idx += 256) {
                int b2 = idx / CP, c = idx - b2 * CP;
                float v = 0.0f;
                if (c < Dn)       v = obs[(((size_t)b2 * Tn + t) * Nn + n) * Dn + c];
                else if (c == Dn) v = g_rar[(b2 * Tn + t) * Nn + n];
                else if (c < Cn)  v = h1s[b2 * 64 + (c - Dn - 1)];
                zs[idx] = v;
            }
            __syncthreads();

            unsigned long long a2[2][2];
            a2[0][0] = 0ull; a2[0][1] = 0ull; a2[1][0] = 0ull; a2[1][1] = 0ull;
            for (int c = 0; c < Cn; c++) {
                unsigned long long z2 = pk2(zs[bb * CP + c]);
                const ulonglong2* wp = (const ulonglong2*)(gWs + c * G3);
                #pragma unroll
                for (int j = 0; j < 2; j++) {
                    ulonglong2 w = wp[32 + c8 + 8 * j];
                    FMA2(a2[j][0], w.x, z2); FMA2(a2[j][1], w.y, z2);
                }
            }
            bool fin = (t == lengths[bb] - 1);
            #pragma unroll
            for (int j = 0; j < 2; j++) {
                float2 lo = up2(a2[j][0]), hi = up2(a2[j][1]);
                float vv[4] = { lo.x, lo.y, hi.x, hi.y };
                #pragma unroll
                for (int e = 0; e < 4; e++) {
                    int d = (c8 + 8 * j) * 4 + e;
                    float cand = tanhf(vv[e] + gb[128 + d]);
                    float h1 = h1s[bb * 64 + d];
                    float u  = us[bb * 64 + d];
                    float h2 = ob ? (1.0f - u) * h1 + u * cand : h1;
                    __stcg(&g_h[((size_t)bb * Nn + n) * Dn + d], h2);
                    if (fin) out[((size_t)bb * Nn + n) * Dn + d] = h2;
                }
            }
        }
        gsync(&g_ctrC2[chunk], 32u * (t + 1));
        gsync(&g_ctrB2[b], 4u * (t + 1));
    }
}

// ---------------- launcher ----------------
extern "C" void kernel_launch(void* const* d_in, const int* in_sizes, int n_in,
                              void* d_out, int out_size) {
    (void)n_in; (void)out_size;
    const float* obs   = (const float*)d_in[0];
    const float* maskp = (const float*)d_in[1];
    const float* avg   = (const float*)d_in[2];
    const float* plm   = (const float*)d_in[3];
    const int* lengths;
    int off;
    if (in_sizes[4] == Bn) { lengths = (const int*)d_in[4];  off = 5; }
    else                   { lengths = (const int*)d_in[25]; off = 4; }
    const float* rarW  = (const float*)d_in[off + 0];
    const float* pfW1  = (const float*)d_in[off + 1];
    const float* pfb1  = (const float*)d_in[off + 2];
    const float* pfW2  = (const float*)d_in[off + 3];
    const float* pfb2  = (const float*)d_in[off + 4];
    const float* pgW1  = (const float*)d_in[off + 5];
    const float* pgb1  = (const float*)d_in[off + 6];
    const float* pgW2  = (const float*)d_in[off + 7];
    const float* pgb2  = (const float*)d_in[off + 8];
    const float* rstW  = (const float*)d_in[off + 9];
    const float* rstB  = (const float*)d_in[off + 10];
    const float* updW  = (const float*)d_in[off + 11];
    const float* updB  = (const float*)d_in[off + 12];
    const float* candW = (const float*)d_in[off + 13];
    const float* candB = (const float*)d_in[off + 14];
    const float* qW    = (const float*)d_in[off + 15];
    const float* qb    = (const float*)d_in[off + 16];
    const float* kW    = (const float*)d_in[off + 17];
    const float* kb    = (const float*)d_in[off + 18];
    const float* vW    = (const float*)d_in[off + 19];
    const float* vb    = (const float*)d_in[off + 20];
    float* out = (float*)d_out;

    cudaFuncSetAttribute(k_main, cudaFuncAttributeMaxDynamicSharedMemorySize, SMEM_B);

    k_pre0<<<Bn, Nn>>>(maskp, avg);
    k_pre1<<<Nn, 128>>>(plm, pfW1, pfb1, pfW2, pfb2, pgW1, pgb1, pgW2, pgb2);
    k_pre2<<<Nn, Nn>>>();
    k_pre3<<<Nn, 256>>>(rstW, rstB, updW, updB, candW, candB);
    k_pre4<<<Cn, WCOLS>>>(qW, qb, kW, kb, vW, vb);

    k_main<<<NCTA, 256, SMEM_B>>>(obs, maskp, rarW, lengths, out);
}

// round 8
// speedup vs baseline: 2.3287x; 1.2387x over previous
#include <cuda_runtime.h>
#include <cstdint>

#define Bn   32
#define Tn   64
#define Nn   128
#define Dn   64
#define Cn   129
#define CP   132
#define CPA  132
#define CKn  16
#define QDn  5
#define NEn  8
#define PLMn 768
#define G3   192
#define NEGV (-9e15f)

#define WCOLS 352          // 322 qkv outputs padded to 88 float4 chunks
#define SWS   356          // smem row stride for qkv weights (89 chunks)
#define NCTA  128u

// ---------------- device scratch ----------------
__device__ __align__(16) float g_qv[Nn * QDn];
__device__ __align__(16) float g_ne[Nn * NEn];
__device__ __align__(16) float g_adj[Nn * Nn];
__device__ __align__(16) float g_rar[Bn * Tn * Nn];
__device__ __align__(16) float g_gW[Nn * Cn * G3];
__device__ __align__(16) float g_gB[Nn * G3];
__device__ __align__(16) float g_WT2[Cn * WCOLS];
__device__ __align__(16) float g_bT[WCOLS];
__device__ __align__(16) float g_h[Bn * Nn * Dn];
__device__ __align__(16) float g_K[Bn * 2 * Nn * CKn];
__device__ __align__(16) float g_V[Bn * 2 * Nn * CP];
__device__ __align__(16) float g_att[Bn * Nn * CP];

__device__ unsigned g_ctrB1[32];   // A->B per-batch (4 CTAs)
__device__ unsigned g_ctrC1[4];    // B->C per-chunk (32 CTAs)
__device__ unsigned g_ctrG;        // end-of-step global (128 CTAs)

// ---------------- helpers ----------------
#define FMA2(acc, w, z) asm("fma.rn.f32x2 %0, %1, %2, %0;" : "+l"(acc) : "l"(w), "l"(z))

__device__ __forceinline__ unsigned long long pk2(float z) {
    unsigned long long r;
    asm("mov.b64 %0, {%1, %1};" : "=l"(r) : "f"(z));
    return r;
}
__device__ __forceinline__ float2 up2(unsigned long long v) {
    float2 r;
    asm("mov.b64 {%0, %1}, %2;" : "=f"(r.x), "=f"(r.y) : "l"(v));
    return r;
}
__device__ __forceinline__ float f4c(const float4& v, int cc) {
    return cc == 0 ? v.x : cc == 1 ? v.y : cc == 2 ? v.z : v.w;
}
__device__ __forceinline__ void cpa16(unsigned dst, const void* src) {
    asm volatile("cp.async.cg.shared.global [%0], [%1], 16;" :: "r"(dst), "l"(src));
}
#define CP_COMMIT() asm volatile("cp.async.commit_group;" ::: "memory")
#define CP_WAIT(N)  asm volatile("cp.async.wait_group %0;" :: "n"(N) : "memory")

// ---------------- precompute ----------------
__global__ void k_pre0(const float* __restrict__ maskp, const float* __restrict__ avg) {
    int b = blockIdx.x, n = threadIdx.x;
    int gtid = b * 128 + n;
    for (int i = gtid; i < Bn * Nn * Dn; i += 4096) g_h[i] = 0.0f;
    if (gtid < 32) g_ctrB1[gtid] = 0;
    if (gtid < 4)  g_ctrC1[gtid] = 0;
    if (gtid == 0) g_ctrG = 0;
    float s = 0.0f;
    for (int t = 0; t < Tn; t++) s += maskp[(b * Tn + t) * Nn + n];
    float inv = 1.0f / (s + 1.0f);
    for (int t = 0; t < Tn; t++)
        g_rar[(b * Tn + t) * Nn + n] = 0.5f * tanhf(avg[(b * Tn + t) * Nn + n] * inv);
}

__global__ void k_pre1(const float* __restrict__ plm,
                       const float* __restrict__ pfW1, const float* __restrict__ pfb1,
                       const float* __restrict__ pfW2, const float* __restrict__ pfb2,
                       const float* __restrict__ pgW1, const float* __restrict__ pgb1,
                       const float* __restrict__ pgW2, const float* __restrict__ pgb2) {
    int n = blockIdx.x, j = threadIdx.x;
    __shared__ float h1[128], h2[128];
    __shared__ float nrm;
    const float* p = plm + (size_t)n * PLMn;
    float a = 0.0f, bv = 0.0f;
    for (int c = 0; c < PLMn; c++) {
        float pv = p[c];
        a  += pv * pfW1[c * 128 + j];
        bv += pv * pgW1[c * 128 + j];
    }
    a += pfb1[j]; bv += pgb1[j];
    h1[j] = a  > 0.0f ? a  : 0.0f;
    h2[j] = bv > 0.0f ? bv : 0.0f;
    __syncthreads();
    if (j < QDn) {
        float s = pfb2[j];
        for (int c = 0; c < 128; c++) s += h1[c] * pfW2[c * QDn + j];
        g_qv[n * QDn + j] = s;
    }
    if (j < NEn) {
        float s = pgb2[j];
        for (int c = 0; c < 128; c++) s += h2[c] * pgW2[c * NEn + j];
        g_ne[n * NEn + j] = s;
    }
    __syncthreads();
    if (j == 0) {
        float s = 0.0f;
        for (int e = 0; e < NEn; e++) { float v = g_ne[n * NEn + e]; s += v * v; }
        nrm = fmaxf(sqrtf(s), 1e-12f);
    }
    __syncthreads();
    if (j < NEn) g_ne[n * NEn + j] /= nrm;
}

__global__ void k_pre2() {
    int n = blockIdx.x, m = threadIdx.x;
    __shared__ float red[128];
    float s = 0.0f;
    for (int e = 0; e < NEn; e++) s += g_ne[n * NEn + e] * g_ne[m * NEn + e];
    red[m] = s;
    __syncthreads();
    for (int st = 64; st > 0; st >>= 1) { if (m < st) red[m] = fmaxf(red[m], red[m + st]); __syncthreads(); }
    float mx = red[0];
    __syncthreads();
    float e = expf(s - mx);
    red[m] = e;
    __syncthreads();
    for (int st = 64; st > 0; st >>= 1) { if (m < st) red[m] += red[m + st]; __syncthreads(); }
    g_adj[n * Nn + m] = e / red[0];
}

__global__ void k_pre3(const float* __restrict__ rstW, const float* __restrict__ rstB,
                       const float* __restrict__ updW, const float* __restrict__ updB,
                       const float* __restrict__ candW, const float* __restrict__ candB) {
    int n = blockIdx.x;
    __shared__ float qv[QDn];
    if (threadIdx.x < QDn) qv[threadIdx.x] = g_qv[n * QDn + threadIdx.x];
    __syncthreads();
    for (int idx = threadIdx.x; idx < Cn * Dn; idx += blockDim.x) {
        int c = idx / Dn, o = idx % Dn;
        float r = 0.0f, u = 0.0f, cd = 0.0f;
        for (int q = 0; q < QDn; q++) {
            float s = qv[q];
            int off = (q * Cn + c) * Dn + o;
            r  += s * rstW[off];
            u  += s * updW[off];
            cd += s * candW[off];
        }
        float* dst = g_gW + ((size_t)n * Cn + c) * G3;
        dst[o] = r; dst[64 + o] = u; dst[128 + o] = cd;
    }
    for (int o = threadIdx.x; o < Dn; o += blockDim.x) {
        float r = 0.0f, u = 0.0f, cd = 0.0f;
        for (int q = 0; q < QDn; q++) {
            float s = qv[q];
            r  += s * rstB[q * Dn + o];
            u  += s * updB[q * Dn + o];
            cd += s * candB[q * Dn + o];
        }
        g_gB[n * G3 + o] = r; g_gB[n * G3 + 64 + o] = u; g_gB[n * G3 + 128 + o] = cd;
    }
}

__global__ void k_pre4(const float* __restrict__ qW, const float* __restrict__ qb,
                       const float* __restrict__ kW, const float* __restrict__ kb,
                       const float* __restrict__ vW, const float* __restrict__ vb) {
    int c = blockIdx.x;       // 0..128
    int j = threadIdx.x;      // 0..351
    float w = 0.0f, bv = 0.0f;
    if (j < 32)       { int h = j >> 4, kk = j & 15;                    w = qW[(h * Cn + c) * CKn + kk]; bv = qb[h * CKn + kk]; }
    else if (j < 64)  { int jj = j - 32; int h = jj >> 4, kk = jj & 15; w = kW[(h * Cn + c) * CKn + kk]; bv = kb[h * CKn + kk]; }
    else if (j < 322) { int jj = j - 64; int h = jj >= Cn; int d = jj - h * Cn; w = vW[(h * Cn + c) * Cn + d]; bv = vb[h * Cn + d]; }
    g_WT2[c * WCOLS + j] = w;
    if (c == 0) g_bT[j] = bv;
}

// ---------------- group barrier ----------------
__device__ __forceinline__ void gsync(unsigned* ctr, unsigned target) {
    __syncthreads();
    if (threadIdx.x == 0) {
        __threadfence();
        atomicAdd(ctr, 1u);
        while (*(volatile unsigned*)ctr < target) { }
        __threadfence();
    }
    __syncthreads();
}

// ---------------- smem layout (floats) ----------------
#define SW_F     (Cn * SWS)            // 45924  (A: qkv W / B: V / C: gate W)
#define BIAS_OFF SW_F                  // 352
#define QSM_OFF  (BIAS_OFF + 352)      // 1024
#define SCR_OFF  (QSM_OFF + 1024)
#define SCR_F    10624
#define SMEM_FLOATS (SCR_OFF + SCR_F)  // 57924
#define SMEM_B   (SMEM_FLOATS * 4)     // 231696 bytes

__global__ void __launch_bounds__(256, 1) k_main(const float* __restrict__ obs,
                                                 const float* __restrict__ maskp,
                                                 const float* __restrict__ rarW,
                                                 const int* __restrict__ lengths,
                                                 float* __restrict__ out) {
    extern __shared__ float sm[];
    float* sW    = sm;
    float* sBias = sm + BIAS_OFF;
    float* qsm   = sm + QSM_OFF;
    float* scr   = sm + SCR_OFF;

    unsigned sm_u  = (unsigned)__cvta_generic_to_shared(sm);
    unsigned sw_u  = sm_u;
    unsigned scr_u = sm_u + SCR_OFF * 4;

    int tid = threadIdx.x;
    int cid = blockIdx.x;
    int b = cid & 31, chunk = cid >> 5, n0 = chunk * 32;

    int w    = tid >> 5, lane = tid & 31;
    int rg   = lane >> 2, co = lane & 3;

    for (int i = tid; i < 352; i += 256) sBias[i] = g_bT[i];

    // prologue: prefetch qkv weights for step 0
    for (int idx = tid; idx < 129 * 88; idx += 256) {
        int row = idx / 88, col = idx - row * 88;
        cpa16(sw_u + (unsigned)(row * SWS + col * 4) * 4, g_WT2 + row * WCOLS + col * 4);
    }
    CP_COMMIT();

    for (int t = 0; t < Tn; t++) {
        // ================= Phase A: qkv projection =================
        {
            float* comb = scr;   // 32 x CPA
            for (int idx = tid; idx < 32 * CPA; idx += 256) {
                int rr = idx / CPA, c = idx - rr * CPA;
                int n = n0 + rr;
                float v = 0.0f;
                if (c < Dn)       v = obs[(((size_t)b * Tn + t) * Nn + n) * Dn + c];
                else if (c == Dn) v = g_rar[(b * Tn + t) * Nn + n];
                else if (c < Cn)  v = __ldcg(&g_h[((size_t)b * Nn + n) * Dn + (c - Dn - 1)]);
                comb[idx] = v;
            }
            CP_WAIT(0);
            __syncthreads();

            int ch0 = 11 * w + co;
            unsigned long long acc[4][3][2];
            #pragma unroll
            for (int i = 0; i < 4; i++)
                #pragma unroll
                for (int j = 0; j < 3; j++) { acc[i][j][0] = 0ull; acc[i][j][1] = 0ull; }

            const float* zb = comb + rg * 4 * CPA;
            #pragma unroll 1
            for (int c4 = 0; c4 < 32; c4++) {
                float4 z4[4];
                #pragma unroll
                for (int i = 0; i < 4; i++) z4[i] = *(const float4*)(zb + i * CPA + c4 * 4);
                #pragma unroll
                for (int cc = 0; cc < 4; cc++) {
                    const float* wr = sW + (c4 * 4 + cc) * SWS + ch0 * 4;
                    ulonglong2 w0 = *(const ulonglong2*)(wr);
                    ulonglong2 w1 = *(const ulonglong2*)(wr + 16);
                    ulonglong2 w2 = *(const ulonglong2*)(wr + 32);
                    #pragma unroll
                    for (int i = 0; i < 4; i++) {
                        unsigned long long z2 = pk2(f4c(z4[i], cc));
                        FMA2(acc[i][0][0], w0.x, z2); FMA2(acc[i][0][1], w0.y, z2);
                        FMA2(acc[i][1][0], w1.x, z2); FMA2(acc[i][1][1], w1.y, z2);
                        FMA2(acc[i][2][0], w2.x, z2); FMA2(acc[i][2][1], w2.y, z2);
                    }
                }
            }
            {   // remainder c = 128
                const float* wr = sW + 128 * SWS + ch0 * 4;
                ulonglong2 w0 = *(const ulonglong2*)(wr);
                ulonglong2 w1 = *(const ulonglong2*)(wr + 16);
                ulonglong2 w2 = *(const ulonglong2*)(wr + 32);
                #pragma unroll
                for (int i = 0; i < 4; i++) {
                    unsigned long long z2 = pk2(zb[i * CPA + 128]);
                    FMA2(acc[i][0][0], w0.x, z2); FMA2(acc[i][0][1], w0.y, z2);
                    FMA2(acc[i][1][0], w1.x, z2); FMA2(acc[i][1][1], w1.y, z2);
                    FMA2(acc[i][2][0], w2.x, z2); FMA2(acc[i][2][1], w2.y, z2);
                }
            }
            // writeout
            #pragma unroll
            for (int i = 0; i < 4; i++) {
                int rr = rg * 4 + i, n = n0 + rr;
                #pragma unroll
                for (int j = 0; j < 3; j++) {
                    if (co + 4 * j > 10) continue;           // masked slot
                    int ch = ch0 + 4 * j;
                    float2 lo = up2(acc[i][j][0]), hi = up2(acc[i][j][1]);
                    float vals[4] = { lo.x, lo.y, hi.x, hi.y };
                    #pragma unroll
                    for (int e = 0; e < 4; e++) {
                        int col = ch * 4 + e;
                        if (col >= 322) continue;
                        float val = vals[e] + sBias[col];
                        if (col < 32) {
                            qsm[rr * 32 + col] = val;
                        } else if (col < 64) {
                            int jj = col - 32;
                            __stcg(&g_K[((b * 2 + (jj >> 4)) * Nn + n) * CKn + (jj & 15)], val);
                        } else {
                            int jj = col - 64;
                            int hh = jj >= Cn;
                            int d = jj - hh * Cn;
                            __stcg(&g_V[(((size_t)b * 2 + hh) * Nn + n) * CP + d], val);
                        }
                    }
                }
            }
        }
        gsync(&g_ctrB1[b], 4u * (t + 1));

        // ================= Phase B: attention =================
        {
            float* Vs  = sW;                     // 2*128*132 floats
            float* Ks2 = scr;                    // 2*128*20 = 5120
            float* Ss  = scr + 5120;             // 32*132 = 4224
            float* rs  = scr + 9344;             // 128
            float* msv = rs + 128;               // 128
            unsigned char* mskb = (unsigned char*)(msv + 128);  // 4096 B

            // K staging (group 1)
            const float* Kbase = g_K + (size_t)(b * 2) * Nn * CKn;
            for (int idx = tid; idx < 2 * 128 * 4; idx += 256) {
                int row = idx >> 2, kq = idx & 3;
                cpa16(scr_u + (unsigned)(row * 20 + kq * 4) * 4, Kbase + row * 16 + kq * 4);
            }
            CP_COMMIT();
            // V staging (group 2)
            const float* Vbase = g_V + (size_t)(b * 2) * Nn * CP;
            for (int idx = tid; idx < 2 * 128 * 33; idx += 256) {
                cpa16(sw_u + (unsigned)idx * 16, Vbase + idx * 4);
            }
            CP_COMMIT();

            if (tid < 128) {
                rs[tid]  = g_rar[(b * Tn + t) * Nn + tid];
                msv[tid] = maskp[((size_t)b * Tn + t) * Nn + tid];
            }
            __syncthreads();
            for (int idx = tid; idx < 32 * 128; idx += 256) {
                int rr2 = idx >> 7, m = idx & 127;
                int n = n0 + rr2;
                unsigned char km = 0;
                if (n != m) {
                    float am  = msv[n] * msv[m];
                    float rm  = -rarW[n * Nn + m] * fabsf(rs[n] - rs[m]);
                    float val = g_adj[n * Nn + m] * (1.0f + rm) * am;
                    km = (val == 0.0f) ? 1 : 0;
                }
                mskb[idx] = km;
            }
            CP_WAIT(1);     // K ready (V still in flight)
            __syncthreads();

            int r  = tid >> 3, c8 = tid & 7;     // QK layout
            int ch = 4 * w + co;                 // PV column chunk (0..31)
            unsigned long long o[4][2];
            #pragma unroll
            for (int i = 0; i < 4; i++) { o[i][0] = 0ull; o[i][1] = 0ull; }
            float ex = 0.0f;
            int row2 = tid >> 3, sub = tid & 7;  // col-128 pass

            for (int h = 0; h < 2; h++) {
                // ---- QK + softmax ----
                float4 q4[4];
                const float4* qrow = (const float4*)(qsm + r * 32 + h * 16);
                q4[0] = qrow[0]; q4[1] = qrow[1]; q4[2] = qrow[2]; q4[3] = qrow[3];
                const float* Kh = Ks2 + h * 128 * 20;

                float sv[16]; float mx = -3.0e38f;
                #pragma unroll
                for (int jm = 0; jm < 16; jm++) {
                    int m = c8 + 8 * jm;
                    const float4* kr = (const float4*)(Kh + m * 20);
                    float d = 0.0f;
                    #pragma unroll
                    for (int kq = 0; kq < 4; kq++) {
                        float4 kv = kr[kq];
                        d += q4[kq].x * kv.x + q4[kq].y * kv.y + q4[kq].z * kv.z + q4[kq].w * kv.w;
                    }
                    d *= 0.25f;
                    d = d > 0.0f ? d : 0.2f * d;
                    if (mskb[(r << 7) + m]) d = NEGV;
                    sv[jm] = d;
                    mx = fmaxf(mx, d);
                }
                #pragma unroll
                for (int oo = 1; oo < 8; oo <<= 1) mx = fmaxf(mx, __shfl_xor_sync(0xffffffffu, mx, oo));
                float sum = 0.0f;
                #pragma unroll
                for (int jm = 0; jm < 16; jm++) { float ee = __expf(sv[jm] - mx); sv[jm] = ee; sum += ee; }
                #pragma unroll
                for (int oo = 1; oo < 8; oo <<= 1) sum += __shfl_xor_sync(0xffffffffu, sum, oo);
                float inv = 1.0f / sum;
                #pragma unroll
                for (int jm = 0; jm < 16; jm++) Ss[r * CP + c8 + 8 * jm] = sv[jm] * inv;
                if (h == 0) { CP_WAIT(0); }      // V ready before first PV
                __syncthreads();

                // ---- PV: warp-partitioned columns ----
                const float* Vh = Vs + (size_t)h * Nn * CP;
                const float* Sb = Ss + rg * 4 * CP;
                #pragma unroll 1
                for (int m4 = 0; m4 < 32; m4++) {
                    float4 p4[4];
                    #pragma unroll
                    for (int i = 0; i < 4; i++) p4[i] = *(const float4*)(Sb + i * CP + m4 * 4);
                    #pragma unroll
                    for (int mm = 0; mm < 4; mm++) {
                        int m = m4 * 4 + mm;
                        ulonglong2 v = *(const ulonglong2*)(Vh + m * CP + ch * 4);
                        #pragma unroll
                        for (int i = 0; i < 4; i++) {
                            unsigned long long z2 = pk2(f4c(p4[i], mm));
                            FMA2(o[i][0], v.x, z2); FMA2(o[i][1], v.y, z2);
                        }
                    }
                }
                // ---- col 128 ----
                {
                    const float* Sr = Ss + row2 * CP;
                    float e = 0.0f;
                    #pragma unroll
                    for (int k = 0; k < 16; k++) {
                        int m = sub * 16 + k;
                        e += Sr[m] * Vh[m * CP + 128];
                    }
                    ex += e;
                }
                __syncthreads();   // protect Ss before next head / exit
            }
            // writeout
            #pragma unroll
            for (int i = 0; i < 4; i++) {
                int n = n0 + rg * 4 + i;
                float2 lo = up2(o[i][0]), hi = up2(o[i][1]);
                float4 a = make_float4(lo.x * 0.5f, lo.y * 0.5f, hi.x * 0.5f, hi.y * 0.5f);
                __stcg((float4*)(g_att + ((size_t)b * Nn + n) * CP) + ch, a);
            }
            ex += __shfl_xor_sync(0xffffffffu, ex, 1);
            ex += __shfl_xor_sync(0xffffffffu, ex, 2);
            ex += __shfl_xor_sync(0xffffffffu, ex, 4);
            if (sub == 0)
                __stcg(&g_att[((size_t)b * Nn + n0 + row2) * CP + 128], ex * 0.5f);
        }
        gsync(&g_ctrC1[chunk], 32u * (t + 1));

        // ================= Phase C: gates (CTA = node) =================
        {
            int n = cid;
            float* gWs = sW;              // 129*192 floats
            float* zs  = scr;             // 32*132
            float* h1s = scr + 4224;      // 32*64
            float* us  = h1s + 2048;      // 32*64
            float* gb  = us + 2048;       // 192
            float* msk = gb + 192;        // 32

            // stage gate weights + att (one group)
            const float* gwsrc = g_gW + (size_t)n * Cn * G3;
            for (int idx = tid; idx < Cn * G3 / 4; idx += 256)
                cpa16(sw_u + (unsigned)idx * 16, gwsrc + idx * 4);
            for (int idx = tid; idx < 32 * 33; idx += 256) {
                int b2 = idx / 33, q = idx - b2 * 33;
                cpa16(scr_u + (unsigned)(b2 * CP + q * 4) * 4,
                      g_att + ((size_t)b2 * Nn + n) * CP + q * 4);
            }
            CP_COMMIT();
            if (tid < G3) gb[tid] = g_gB[n * G3 + tid];
            if (tid < 32) msk[tid] = maskp[((size_t)tid * Tn + t) * Nn + n];
            CP_WAIT(0);
            __syncthreads();

            // ---- r/u GEMM: warp w owns chunks {4w+co} ----
            int ch = 4 * w + co;          // 0..31 -> cols ch*4..+3
            unsigned long long a1[4][2];
            #pragma unroll
            for (int i = 0; i < 4; i++) { a1[i][0] = 0ull; a1[i][1] = 0ull; }
            const float* zb = zs + rg * 4 * CP;
            #pragma unroll 1
            for (int c4 = 0; c4 < 32; c4++) {
                float4 z4[4];
                #pragma unroll
                for (int i = 0; i < 4; i++) z4[i] = *(const float4*)(zb + i * CP + c4 * 4);
                #pragma unroll
                for (int cc = 0; cc < 4; cc++) {
                    ulonglong2 wv = *(const ulonglong2*)(gWs + (c4 * 4 + cc) * G3 + ch * 4);
                    #pragma unroll
                    for (int i = 0; i < 4; i++) {
                        unsigned long long z2 = pk2(f4c(z4[i], cc));
                        FMA2(a1[i][0], wv.x, z2); FMA2(a1[i][1], wv.y, z2);
                    }
                }
            }
            {   // remainder c = 128
                ulonglong2 wv = *(const ulonglong2*)(gWs + 128 * G3 + ch * 4);
                #pragma unroll
                for (int i = 0; i < 4; i++) {
                    unsigned long long z2 = pk2(zb[i * CP + 128]);
                    FMA2(a1[i][0], wv.x, z2); FMA2(a1[i][1], wv.y, z2);
                }
            }
            // epilogue: warps 0-3 produce h1 (r), warps 4-7 produce u
            #pragma unroll
            for (int i = 0; i < 4; i++) {
                int bb = rg * 4 + i;
                bool ob = msk[bb] > 0.0f;
                float2 lo = up2(a1[i][0]), hi = up2(a1[i][1]);
                float vals[4] = { lo.x, lo.y, hi.x, hi.y };
                if (ch < 16) {
                    int o0 = ch * 4;
                    float4 hv = __ldcg((const float4*)&g_h[((size_t)bb * Nn + n) * Dn + o0]);
                    float4 h1v;
                    float g0 = 1.0f / (1.0f + __expf(-(vals[0] + gb[o0 + 0])));
                    float g1 = 1.0f / (1.0f + __expf(-(vals[1] + gb[o0 + 1])));
                    float g2 = 1.0f / (1.0f + __expf(-(vals[2] + gb[o0 + 2])));
                    float g3 = 1.0f / (1.0f + __expf(-(vals[3] + gb[o0 + 3])));
                    h1v.x = ob ? g0 * hv.x : hv.x;
                    h1v.y = ob ? g1 * hv.y : hv.y;
                    h1v.z = ob ? g2 * hv.z : hv.z;
                    h1v.w = ob ? g3 * hv.w : hv.w;
                    *(float4*)&h1s[bb * 64 + o0] = h1v;
                } else {
                    int o0 = ch * 4;           // 64..127
                    int d0 = o0 - 64;
                    float4 uv;
                    uv.x = 1.0f / (1.0f + __expf(-(vals[0] + gb[o0 + 0])));
                    uv.y = 1.0f / (1.0f + __expf(-(vals[1] + gb[o0 + 1])));
                    uv.z = 1.0f / (1.0f + __expf(-(vals[2] + gb[o0 + 2])));
                    uv.w = 1.0f / (1.0f + __expf(-(vals[3] + gb[o0 + 3])));
                    *(float4*)&us[bb * 64 + d0] = uv;
                }
            }
            __syncthreads();

            // zs2 = [x, h1]
            for (int idx = tid; idx < 32 * CP; idx += 256) {
                int b2 = idx / CP, c = idx - b2 * CP;
                float v = 0.0f;
                if (c < Dn)       v = obs[(((size_t)b2 * Tn + t) * Nn + n) * Dn + c];
                else if (c == Dn) v = g_rar[(b2 * Tn + t) * Nn + n];
                else if (c < Cn)  v = h1s[b2 * 64 + (c - Dn - 1)];
                zs[idx] = v;
            }
            __syncthreads();

            // ---- cand GEMM: warp w owns chunks {32+2w+(lane&1)} ----
            int ch2 = 32 + 2 * w + (lane & 1);   // 32..47
            int bg  = lane >> 1;                 // 0..15 -> batches bg*2, bg*2+1
            unsigned long long a2[2][2];
            a2[0][0] = 0ull; a2[0][1] = 0ull; a2[1][0] = 0ull; a2[1][1] = 0ull;
            const float* zb2 = zs + bg * 2 * CP;
            #pragma unroll 1
            for (int c4 = 0; c4 < 32; c4++) {
                float4 z4[2];
                z4[0] = *(const float4*)(zb2 + c4 * 4);
                z4[1] = *(const float4*)(zb2 + CP + c4 * 4);
                #pragma unroll
                for (int cc = 0; cc < 4; cc++) {
                    ulonglong2 wv = *(const ulonglong2*)(gWs + (c4 * 4 + cc) * G3 + ch2 * 4);
                    #pragma unroll
                    for (int i = 0; i < 2; i++) {
                        unsigned long long z2 = pk2(f4c(z4[i], cc));
                        FMA2(a2[i][0], wv.x, z2); FMA2(a2[i][1], wv.y, z2);
                    }
                }
            }
            {   // remainder c = 128
                ulonglong2 wv = *(const ulonglong2*)(gWs + 128 * G3 + ch2 * 4);
                #pragma unroll
                for (int i = 0; i < 2; i++) {
                    unsigned long long z2 = pk2(zb2[i * CP + 128]);
                    FMA2(a2[i][0], wv.x, z2); FMA2(a2[i][1], wv.y, z2);
                }
            }
            // final epilogue
            #pragma unroll
            for (int i = 0; i < 2; i++) {
                int bb = bg * 2 + i;
                bool ob = msk[bb] > 0.0f;
                bool fin = (t == lengths[bb] - 1);
                int d0 = (ch2 - 32) * 4;
                float2 lo = up2(a2[i][0]), hi = up2(a2[i][1]);
                float vals[4] = { lo.x, lo.y, hi.x, hi.y };
                float4 h1v = *(const float4*)&h1s[bb * 64 + d0];
                float4 uv  = *(const float4*)&us[bb * 64 + d0];
                float4 h2;
                {
                    float c0 = tanhf(vals[0] + gb[128 + d0 + 0]);
                    float c1 = tanhf(vals[1] + gb[128 + d0 + 1]);
                    float c2 = tanhf(vals[2] + gb[128 + d0 + 2]);
                    float c3 = tanhf(vals[3] + gb[128 + d0 + 3]);
                    h2.x = ob ? (1.0f - uv.x) * h1v.x + uv.x * c0 : h1v.x;
                    h2.y = ob ? (1.0f - uv.y) * h1v.y + uv.y * c1 : h1v.y;
                    h2.z = ob ? (1.0f - uv.z) * h1v.z + uv.z * c2 : h1v.z;
                    h2.w = ob ? (1.0f - uv.w) * h1v.w + uv.w * c3 : h1v.w;
                }
                __stcg((float4*)&g_h[((size_t)bb * Nn + n) * Dn + d0], h2);
                if (fin) *(float4*)&out[((size_t)bb * Nn + n) * Dn + d0] = h2;
            }

            // prefetch next step's qkv weights (constant data) behind the barrier
            __syncthreads();
            for (int idx = tid; idx < 129 * 88; idx += 256) {
                int row = idx / 88, col = idx - row * 88;
                cpa16(sw_u + (unsigned)(row * SWS + col * 4) * 4, g_WT2 + row * WCOLS + col * 4);
            }
            CP_COMMIT();
        }
        gsync(&g_ctrG, 128u * (t + 1));
    }
}

// ---------------- launcher ----------------
extern "C" void kernel_launch(void* const* d_in, const int* in_sizes, int n_in,
                              void* d_out, int out_size) {
    (void)n_in; (void)out_size;
    const float* obs   = (const float*)d_in[0];
    const float* maskp = (const float*)d_in[1];
    const float* avg   = (const float*)d_in[2];
    const float* plm   = (const float*)d_in[3];
    const int* lengths;
    int off;
    if (in_sizes[4] == Bn) { lengths = (const int*)d_in[4];  off = 5; }
    else                   { lengths = (const int*)d_in[25]; off = 4; }
    const float* rarW  = (const float*)d_in[off + 0];
    const float* pfW1  = (const float*)d_in[off + 1];
    const float* pfb1  = (const float*)d_in[off + 2];
    const float* pfW2  = (const float*)d_in[off + 3];
    const float* pfb2  = (const float*)d_in[off + 4];
    const float* pgW1  = (const float*)d_in[off + 5];
    const float* pgb1  = (const float*)d_in[off + 6];
    const float* pgW2  = (const float*)d_in[off + 7];
    const float* pgb2  = (const float*)d_in[off + 8];
    const float* rstW  = (const float*)d_in[off + 9];
    const float* rstB  = (const float*)d_in[off + 10];
    const float* updW  = (const float*)d_in[off + 11];
    const float* updB  = (const float*)d_in[off + 12];
    const float* candW = (const float*)d_in[off + 13];
    const float* candB = (const float*)d_in[off + 14];
    const float* qW    = (const float*)d_in[off + 15];
    const float* qb    = (const float*)d_in[off + 16];
    const float* kW    = (const float*)d_in[off + 17];
    const float* kb    = (const float*)d_in[off + 18];
    const float* vW    = (const float*)d_in[off + 19];
    const float* vb    = (const float*)d_in[off + 20];
    float* outp = (float*)d_out;

    cudaFuncSetAttribute(k_main, cudaFuncAttributeMaxDynamicSharedMemorySize, SMEM_B);

    k_pre0<<<Bn, Nn>>>(maskp, avg);
    k_pre1<<<Nn, 128>>>(plm, pfW1, pfb1, pfW2, pfb2, pgW1, pgb1, pgW2, pgb2);
    k_pre2<<<Nn, Nn>>>();
    k_pre3<<<Nn, 256>>>(rstW, rstB, updW, updB, candW, candB);
    k_pre4<<<Cn, WCOLS>>>(qW, qb, kW, kb, vW, vb);

    k_main<<<NCTA, 256, SMEM_B>>>(obs, maskp, rarW, lengths, outp);
}

// round 9
// speedup vs baseline: 2.4535x; 1.0536x over previous
#include <cuda_runtime.h>
#include <cstdint>

#define Bn   32
#define Tn   64
#define Nn   128
#define Dn   64
#define Cn   129
#define CP   132
#define QDn  5
#define NEn  8
#define PLMn 768
#define G3   192
#define NEGV (-9e15f)

#define WCOLS 352          // qkv weight columns (used: 0..327, padded)
#define VROW  264          // g_V row stride: h0 at [0,129), h1 at [132,261)
#define NCTA  128u

// ---------------- device scratch ----------------
__device__ __align__(16) float g_qv[Nn * QDn];
__device__ __align__(16) float g_ne[Nn * NEn];
__device__ __align__(16) float g_adj[Nn * Nn];
__device__ __align__(16) float g_rar[Bn * Tn * Nn];
__device__ __align__(16) float g_gW[Nn * Cn * G3];
__device__ __align__(16) float g_gB[Nn * G3];
__device__ __align__(16) float g_WT2[Cn * WCOLS];
__device__ __align__(16) float g_bT[WCOLS];
__device__ __align__(16) float g_Q[2 * Bn * Nn * 32];
__device__ __align__(16) float g_K[2 * Bn * Nn * 32];
__device__ __align__(16) float g_V[2 * (size_t)Bn * Nn * VROW];
__device__ __align__(16) float g_att[(size_t)Bn * Nn * CP];

__device__ unsigned g_ctrG;        // global barrier (128 CTAs)
__device__ unsigned g_ctrGrp[4];   // group barrier (32 contiguous CTAs)

// ---------------- helpers ----------------
#define FMA2(acc, w, z) asm("fma.rn.f32x2 %0, %1, %2, %0;" : "+l"(acc) : "l"(w), "l"(z))

__device__ __forceinline__ unsigned long long pk2(float z) {
    unsigned long long r;
    asm("mov.b64 %0, {%1, %1};" : "=l"(r) : "f"(z));
    return r;
}
__device__ __forceinline__ float2 up2(unsigned long long v) {
    float2 r;
    asm("mov.b64 {%0, %1}, %2;" : "=f"(r.x), "=f"(r.y) : "l"(v));
    return r;
}
__device__ __forceinline__ float f4c(const float4& v, int cc) {
    return cc == 0 ? v.x : cc == 1 ? v.y : cc == 2 ? v.z : v.w;
}
__device__ __forceinline__ void cpa16(unsigned dst, const void* src) {
    asm volatile("cp.async.cg.shared.global [%0], [%1], 16;" :: "r"(dst), "l"(src));
}
#define CP_COMMIT() asm volatile("cp.async.commit_group;" ::: "memory")
#define CP_WAIT(N)  asm volatile("cp.async.wait_group %0;" :: "n"(N) : "memory")

// ---------------- precompute ----------------
__global__ void k_pre0(const float* __restrict__ maskp, const float* __restrict__ avg) {
    int b = blockIdx.x, n = threadIdx.x;
    int gtid = b * 128 + n;
    if (gtid == 0) g_ctrG = 0;
    if (gtid < 4)  g_ctrGrp[gtid] = 0;
    float s = 0.0f;
    for (int t = 0; t < Tn; t++) s += maskp[(b * Tn + t) * Nn + n];
    float inv = 1.0f / (s + 1.0f);
    for (int t = 0; t < Tn; t++)
        g_rar[(b * Tn + t) * Nn + n] = 0.5f * tanhf(avg[(b * Tn + t) * Nn + n] * inv);
}

__global__ void k_pre1(const float* __restrict__ plm,
                       const float* __restrict__ pfW1, const float* __restrict__ pfb1,
                       const float* __restrict__ pfW2, const float* __restrict__ pfb2,
                       const float* __restrict__ pgW1, const float* __restrict__ pgb1,
                       const float* __restrict__ pgW2, const float* __restrict__ pgb2) {
    int n = blockIdx.x, j = threadIdx.x;
    __shared__ float h1[128], h2[128];
    __shared__ float nrm;
    const float* p = plm + (size_t)n * PLMn;
    float a = 0.0f, bv = 0.0f;
    for (int c = 0; c < PLMn; c++) {
        float pv = p[c];
        a  += pv * pfW1[c * 128 + j];
        bv += pv * pgW1[c * 128 + j];
    }
    a += pfb1[j]; bv += pgb1[j];
    h1[j] = a  > 0.0f ? a  : 0.0f;
    h2[j] = bv > 0.0f ? bv : 0.0f;
    __syncthreads();
    if (j < QDn) {
        float s = pfb2[j];
        for (int c = 0; c < 128; c++) s += h1[c] * pfW2[c * QDn + j];
        g_qv[n * QDn + j] = s;
    }
    if (j < NEn) {
        float s = pgb2[j];
        for (int c = 0; c < 128; c++) s += h2[c] * pgW2[c * NEn + j];
        g_ne[n * NEn + j] = s;
    }
    __syncthreads();
    if (j == 0) {
        float s = 0.0f;
        for (int e = 0; e < NEn; e++) { float v = g_ne[n * NEn + e]; s += v * v; }
        nrm = fmaxf(sqrtf(s), 1e-12f);
    }
    __syncthreads();
    if (j < NEn) g_ne[n * NEn + j] /= nrm;
}

__global__ void k_pre2() {
    int n = blockIdx.x, m = threadIdx.x;
    __shared__ float red[128];
    float s = 0.0f;
    for (int e = 0; e < NEn; e++) s += g_ne[n * NEn + e] * g_ne[m * NEn + e];
    red[m] = s;
    __syncthreads();
    for (int st = 64; st > 0; st >>= 1) { if (m < st) red[m] = fmaxf(red[m], red[m + st]); __syncthreads(); }
    float mx = red[0];
    __syncthreads();
    float e = expf(s - mx);
    red[m] = e;
    __syncthreads();
    for (int st = 64; st > 0; st >>= 1) { if (m < st) red[m] += red[m + st]; __syncthreads(); }
    g_adj[n * Nn + m] = e / red[0];
}

__global__ void k_pre3(const float* __restrict__ rstW, const float* __restrict__ rstB,
                       const float* __restrict__ updW, const float* __restrict__ updB,
                       const float* __restrict__ candW, const float* __restrict__ candB) {
    int n = blockIdx.x;
    __shared__ float qv[QDn];
    if (threadIdx.x < QDn) qv[threadIdx.x] = g_qv[n * QDn + threadIdx.x];
    __syncthreads();
    for (int idx = threadIdx.x; idx < Cn * Dn; idx += blockDim.x) {
        int c = idx / Dn, o = idx % Dn;
        float r = 0.0f, u = 0.0f, cd = 0.0f;
        for (int q = 0; q < QDn; q++) {
            float s = qv[q];
            int off = (q * Cn + c) * Dn + o;
            r  += s * rstW[off];
            u  += s * updW[off];
            cd += s * candW[off];
        }
        float* dst = g_gW + ((size_t)n * Cn + c) * G3;
        dst[o] = r; dst[64 + o] = u; dst[128 + o] = cd;
    }
    for (int o = threadIdx.x; o < Dn; o += blockDim.x) {
        float r = 0.0f, u = 0.0f, cd = 0.0f;
        for (int q = 0; q < QDn; q++) {
            float s = qv[q];
            r  += s * rstB[q * Dn + o];
            u  += s * updB[q * Dn + o];
            cd += s * candB[q * Dn + o];
        }
        g_gB[n * G3 + o] = r; g_gB[n * G3 + 64 + o] = u; g_gB[n * G3 + 128 + o] = cd;
    }
}

// qkv weights, new column order: Q[0,32) K[32,64) Vh0[64,193) pad[193,196) Vh1[196,325)
__global__ void k_pre4(const float* __restrict__ qW, const float* __restrict__ qb,
                       const float* __restrict__ kW, const float* __restrict__ kb,
                       const float* __restrict__ vW, const float* __restrict__ vb) {
    int c = blockIdx.x;       // 0..128
    int j = threadIdx.x;      // 0..351
    float w = 0.0f, bv = 0.0f;
    if (j < 32) {
        int h = j >> 4, kk = j & 15;
        w = qW[(h * Cn + c) * 16 + kk]; bv = qb[h * 16 + kk];
    } else if (j < 64) {
        int jj = j - 32; int h = jj >> 4, kk = jj & 15;
        w = kW[(h * Cn + c) * 16 + kk]; bv = kb[h * 16 + kk];
    } else if (j <= 192) {
        int d = j - 64;
        w = vW[((size_t)c) * Cn + d]; bv = vb[d];
    } else if (j >= 196 && j <= 324) {
        int d = j - 196;
        w = vW[((size_t)(Cn + c)) * Cn + d]; bv = vb[Cn + d];
    }
    g_WT2[c * WCOLS + j] = w;
    if (c == 0) g_bT[j] = bv;
}

// ---------------- group barrier ----------------
__device__ __forceinline__ void gsync(unsigned* ctr, unsigned target) {
    __syncthreads();
    if (threadIdx.x == 0) {
        __threadfence();
        atomicAdd(ctr, 1u);
        while (*(volatile unsigned*)ctr < target) { }
        __threadfence();
    }
    __syncthreads();
}

// ---------------- smem layout (floats) ----------------
// OV  [0, 45408)          A': qkv weights (129x352) / B: Vs (128x264=33792) / C: gW (129x192=24768)
// SCR [45408, 55648)      per-phase scratch (10240)
// HS  [55648, 57760)      resident h: 32 x 66
// SB  [57760, 58088)      qkv bias (328)
#define OV_F   45408
#define SCR_F  10240
#define HS_OFF (OV_F + SCR_F)
#define SB_OFF (HS_OFF + 2112)
#define SMEM_FLOATS (SB_OFF + 328)       // 58088
#define SMEM_B (SMEM_FLOATS * 4)         // 232352 bytes

__global__ void __launch_bounds__(256, 1) k_main(const float* __restrict__ obs,
                                                 const float* __restrict__ maskp,
                                                 const float* __restrict__ rarW,
                                                 const int* __restrict__ lengths,
                                                 float* __restrict__ out) {
    extern __shared__ float sm[];
    float* OV    = sm;
    float* scr   = sm + OV_F;
    float* hs    = sm + HS_OFF;
    float* sBias = sm + SB_OFF;

    unsigned sm_u  = (unsigned)__cvta_generic_to_shared(sm);
    unsigned ov_u  = sm_u;
    unsigned scr_u = sm_u + OV_F * 4;

    int tid = threadIdx.x;
    int cid = blockIdx.x;
    int n   = cid;                       // node identity (A'/C)
    int b   = cid & 31, n0 = (cid >> 5) * 32;   // batch identity (B)
    int grp = cid >> 5;

    int w = tid >> 5, lane = tid & 31;
    int rg = lane >> 2, co = lane & 3;
    int ch0 = 11 * w + co;

    // init: h = 0, bias resident
    for (int i = tid; i < 2112; i += 256) hs[i] = 0.0f;
    for (int i = tid; i < 328; i += 256) sBias[i] = g_bT[i];
    __syncthreads();

    // prefetch qkv weights for A'(0)
    for (int idx = tid; idx < 129 * 88; idx += 256) {
        int row = idx / 88, col = idx - row * 88;
        cpa16(ov_u + (unsigned)(row * WCOLS + col * 4) * 4, g_WT2 + row * WCOLS + col * 4);
    }
    CP_COMMIT();

    for (int tt = 0; tt <= Tn; tt++) {
        // ================= Phase A'(tt): node-major qkv (skip at tt==Tn) ====
        if (tt < Tn) {
            int buf = tt & 1;
            float* comb = scr;   // 32 batches x 132
            for (int idx = tid; idx < 32 * CP; idx += 256) {
                int bb = idx / CP, c = idx - bb * CP;
                float v = 0.0f;
                if (c < Dn)       v = obs[(((size_t)bb * Tn + tt) * Nn + n) * Dn + c];
                else if (c == Dn) v = g_rar[(bb * Tn + tt) * Nn + n];
                else if (c < Cn)  v = hs[bb * 66 + (c - Dn - 1)];
                comb[idx] = v;
            }
            CP_WAIT(0);
            __syncthreads();

            unsigned long long acc[4][3][2];
            #pragma unroll
            for (int i = 0; i < 4; i++)
                #pragma unroll
                for (int j = 0; j < 3; j++) { acc[i][j][0] = 0ull; acc[i][j][1] = 0ull; }

            const float* zb = comb + rg * 4 * CP;
            #pragma unroll 1
            for (int c4 = 0; c4 < 32; c4++) {
                float4 z4[4];
                #pragma unroll
                for (int i = 0; i < 4; i++) z4[i] = *(const float4*)(zb + i * CP + c4 * 4);
                #pragma unroll
                for (int cc = 0; cc < 4; cc++) {
                    const float* wr = OV + (c4 * 4 + cc) * WCOLS + ch0 * 4;
                    ulonglong2 w0 = *(const ulonglong2*)(wr);
                    ulonglong2 w1 = *(const ulonglong2*)(wr + 16);
                    ulonglong2 w2 = *(const ulonglong2*)(wr + 32);
                    #pragma unroll
                    for (int i = 0; i < 4; i++) {
                        unsigned long long z2 = pk2(f4c(z4[i], cc));
                        FMA2(acc[i][0][0], w0.x, z2); FMA2(acc[i][0][1], w0.y, z2);
                        FMA2(acc[i][1][0], w1.x, z2); FMA2(acc[i][1][1], w1.y, z2);
                        FMA2(acc[i][2][0], w2.x, z2); FMA2(acc[i][2][1], w2.y, z2);
                    }
                }
            }
            {   // remainder c = 128
                const float* wr = OV + 128 * WCOLS + ch0 * 4;
                ulonglong2 w0 = *(const ulonglong2*)(wr);
                ulonglong2 w1 = *(const ulonglong2*)(wr + 16);
                ulonglong2 w2 = *(const ulonglong2*)(wr + 32);
                #pragma unroll
                for (int i = 0; i < 4; i++) {
                    unsigned long long z2 = pk2(zb[i * CP + 128]);
                    FMA2(acc[i][0][0], w0.x, z2); FMA2(acc[i][0][1], w0.y, z2);
                    FMA2(acc[i][1][0], w1.x, z2); FMA2(acc[i][1][1], w1.y, z2);
                    FMA2(acc[i][2][0], w2.x, z2); FMA2(acc[i][2][1], w2.y, z2);
                }
            }
            // coalesced float4 writeout
            float* Qb = g_Q + (size_t)buf * Bn * Nn * 32;
            float* Kb = g_K + (size_t)buf * Bn * Nn * 32;
            float* Vb = g_V + (size_t)buf * Bn * Nn * VROW;
            #pragma unroll
            for (int i = 0; i < 4; i++) {
                int bb = rg * 4 + i;
                #pragma unroll
                for (int j = 0; j < 3; j++) {
                    if (co + 4 * j > 10) continue;
                    int ch = ch0 + 4 * j;
                    if (ch >= 82) continue;
                    float2 lo = up2(acc[i][j][0]), hi = up2(acc[i][j][1]);
                    float4 bias4 = *(const float4*)&sBias[ch * 4];
                    float4 v4 = make_float4(lo.x + bias4.x, lo.y + bias4.y,
                                            hi.x + bias4.z, hi.y + bias4.w);
                    if (ch < 8)        *(float4*)&Qb[((size_t)bb * Nn + n) * 32 + ch * 4] = v4;
                    else if (ch < 16)  *(float4*)&Kb[((size_t)bb * Nn + n) * 32 + ch * 4 - 32] = v4;
                    else               *(float4*)&Vb[((size_t)bb * Nn + n) * VROW + ch * 4 - 64] = v4;
                }
            }
        }
        if (tt == Tn) break;
        int t = tt;
        gsync(&g_ctrG, 128u * (t + 1));

        // ================= Phase B: attention (batch-major) =================
        {
            int buf = t & 1;
            float* Vs  = OV;                 // 128 x 264 = 33792
            float* Ks  = scr;                // 128 x 36  = 4608
            float* Ss  = scr + 4608;         // 32 x 132  = 4224
            float* Qs  = scr + 8832;         // 32 x 32   = 1024
            float* rs  = scr + 9856;         // 128
            float* msv = scr + 9984;         // 128
            unsigned* mskw = (unsigned*)(scr + 10112);  // 128 words

            const float* Kg = g_K + (size_t)buf * Bn * Nn * 32 + (size_t)b * Nn * 32;
            const float* Qg = g_Q + (size_t)buf * Bn * Nn * 32 + (size_t)b * Nn * 32;
            const float* Vg = g_V + (size_t)buf * Bn * Nn * VROW + (size_t)b * Nn * VROW;

            // group1: K + Q
            for (int idx = tid; idx < 128 * 8; idx += 256) {
                int row = idx >> 3, q = idx & 7;
                cpa16(scr_u + (unsigned)(row * 36 + q * 4) * 4, Kg + row * 32 + q * 4);
            }
            {
                int row = tid >> 3, q = tid & 7;
                cpa16(scr_u + (unsigned)(8832 + row * 32 + q * 4) * 4, Qg + (n0 + row) * 32 + q * 4);
            }
            CP_COMMIT();
            // group2: V
            for (int idx = tid; idx < 128 * 66; idx += 256)
                cpa16(ov_u + (unsigned)idx * 16, Vg + idx * 4);
            CP_COMMIT();

            if (tid < 128) {
                rs[tid]  = g_rar[(b * Tn + t) * Nn + tid];
                msv[tid] = maskp[((size_t)b * Tn + t) * Nn + tid];
            }
            __syncthreads();
            // mask bits: word (r, wseg) covers m = wseg*32..+31
            if (tid < 128) {
                int r = tid >> 2, ws = tid & 3;
                int nn = n0 + r;
                unsigned word = 0;
                float rn = rs[nn], mn = msv[nn];
                for (int mm = 0; mm < 32; mm++) {
                    int m = ws * 32 + mm;
                    if (nn != m) {
                        float am  = mn * msv[m];
                        float rm  = -rarW[nn * Nn + m] * fabsf(rn - rs[m]);
                        float val = g_adj[nn * Nn + m] * (1.0f + rm) * am;
                        if (val == 0.0f) word |= (1u << mm);
                    }
                }
                mskw[tid] = word;
            }
            CP_WAIT(1);      // K + Q ready
            __syncthreads();

            int r2 = tid >> 3, c8 = tid & 7;
            int ch = 4 * w + co;
            unsigned long long o[4][2];
            #pragma unroll
            for (int i = 0; i < 4; i++) { o[i][0] = 0ull; o[i][1] = 0ull; }
            float ex = 0.0f;

            for (int h = 0; h < 2; h++) {
                float4 q4[4];
                const float4* qrow = (const float4*)(Qs + r2 * 32 + h * 16);
                q4[0] = qrow[0]; q4[1] = qrow[1]; q4[2] = qrow[2]; q4[3] = qrow[3];

                float sv[16]; float mx = -3.0e38f;
                #pragma unroll
                for (int jm = 0; jm < 16; jm++) {
                    int m = c8 + 8 * jm;
                    const float4* kr = (const float4*)(Ks + m * 36 + h * 16);
                    float d = 0.0f;
                    #pragma unroll
                    for (int kq = 0; kq < 4; kq++) {
                        float4 kv = kr[kq];
                        d += q4[kq].x * kv.x + q4[kq].y * kv.y + q4[kq].z * kv.z + q4[kq].w * kv.w;
                    }
                    d *= 0.25f;
                    d = d > 0.0f ? d : 0.2f * d;
                    if ((mskw[(r2 << 2) + (m >> 5)] >> (m & 31)) & 1u) d = NEGV;
                    sv[jm] = d;
                    mx = fmaxf(mx, d);
                }
                #pragma unroll
                for (int oo = 1; oo < 8; oo <<= 1) mx = fmaxf(mx, __shfl_xor_sync(0xffffffffu, mx, oo));
                float sum = 0.0f;
                #pragma unroll
                for (int jm = 0; jm < 16; jm++) { float ee = __expf(sv[jm] - mx); sv[jm] = ee; sum += ee; }
                #pragma unroll
                for (int oo = 1; oo < 8; oo <<= 1) sum += __shfl_xor_sync(0xffffffffu, sum, oo);
                float inv = 1.0f / sum;
                #pragma unroll
                for (int jm = 0; jm < 16; jm++) Ss[r2 * CP + c8 + 8 * jm] = sv[jm] * inv;
                if (h == 0) { CP_WAIT(0); }    // V ready before first PV
                __syncthreads();

                const float* Vh = Vs + h * 132;
                const float* Sb = Ss + rg * 4 * CP;
                #pragma unroll 1
                for (int m4 = 0; m4 < 32; m4++) {
                    float4 p4[4];
                    #pragma unroll
                    for (int i = 0; i < 4; i++) p4[i] = *(const float4*)(Sb + i * CP + m4 * 4);
                    #pragma unroll
                    for (int mm = 0; mm < 4; mm++) {
                        int m = m4 * 4 + mm;
                        ulonglong2 v = *(const ulonglong2*)(Vh + m * VROW + ch * 4);
                        #pragma unroll
                        for (int i = 0; i < 4; i++) {
                            unsigned long long z2 = pk2(f4c(p4[i], mm));
                            FMA2(o[i][0], v.x, z2); FMA2(o[i][1], v.y, z2);
                        }
                    }
                }
                {   // column d = 128
                    int row = tid >> 3, sub = tid & 7;
                    const float* Sr = Ss + row * CP;
                    float e = 0.0f;
                    #pragma unroll
                    for (int k = 0; k < 16; k++) {
                        int m = sub * 16 + k;
                        e += Sr[m] * Vh[m * VROW + 128];
                    }
                    ex += e;
                }
                __syncthreads();
            }
            #pragma unroll
            for (int i = 0; i < 4; i++) {
                int nn = n0 + rg * 4 + i;
                float2 lo = up2(o[i][0]), hi = up2(o[i][1]);
                float4 a = make_float4(lo.x * 0.5f, lo.y * 0.5f, hi.x * 0.5f, hi.y * 0.5f);
                *(float4*)&g_att[((size_t)b * Nn + nn) * CP + ch * 4] = a;
            }
            ex += __shfl_xor_sync(0xffffffffu, ex, 1);
            ex += __shfl_xor_sync(0xffffffffu, ex, 2);
            ex += __shfl_xor_sync(0xffffffffu, ex, 4);
            if ((tid & 7) == 0)
                g_att[((size_t)b * Nn + n0 + (tid >> 3)) * CP + 128] = ex * 0.5f;
        }
        gsync(&g_ctrGrp[grp], 32u * (t + 1));

        // ================= Phase C: gates (node-major, h in smem) ===========
        {
            float* gWs = OV;              // 129*192 = 24768
            float* zs  = scr;             // 32*132
            float* h1s = scr + 4224;      // 32*64
            float* us  = h1s + 2048;      // 32*64
            float* gb  = us + 2048;       // 192
            float* msk = gb + 192;        // 32

            const float* gwsrc = g_gW + (size_t)n * Cn * G3;
            for (int idx = tid; idx < Cn * G3 / 4; idx += 256)
                cpa16(ov_u + (unsigned)idx * 16, gwsrc + idx * 4);
            for (int idx = tid; idx < 32 * 33; idx += 256) {
                int b2 = idx / 33, q = idx - b2 * 33;
                cpa16(scr_u + (unsigned)(b2 * CP + q * 4) * 4,
                      g_att + ((size_t)b2 * Nn + n) * CP + q * 4);
            }
            CP_COMMIT();
            if (tid < G3) gb[tid] = g_gB[n * G3 + tid];
            if (tid < 32) msk[tid] = maskp[((size_t)tid * Tn + t) * Nn + n];
            CP_WAIT(0);
            __syncthreads();

            // ---- r/u GEMM ----
            int ch = 4 * w + co;
            unsigned long long a1[4][2];
            #pragma unroll
            for (int i = 0; i < 4; i++) { a1[i][0] = 0ull; a1[i][1] = 0ull; }
            const float* zb = zs + rg * 4 * CP;
            #pragma unroll 1
            for (int c4 = 0; c4 < 32; c4++) {
                float4 z4[4];
                #pragma unroll
                for (int i = 0; i < 4; i++) z4[i] = *(const float4*)(zb + i * CP + c4 * 4);
                #pragma unroll
                for (int cc = 0; cc < 4; cc++) {
                    ulonglong2 wv = *(const ulonglong2*)(gWs + (c4 * 4 + cc) * G3 + ch * 4);
                    #pragma unroll
                    for (int i = 0; i < 4; i++) {
                        unsigned long long z2 = pk2(f4c(z4[i], cc));
                        FMA2(a1[i][0], wv.x, z2); FMA2(a1[i][1], wv.y, z2);
                    }
                }
            }
            {
                ulonglong2 wv = *(const ulonglong2*)(gWs + 128 * G3 + ch * 4);
                #pragma unroll
                for (int i = 0; i < 4; i++) {
                    unsigned long long z2 = pk2(zb[i * CP + 128]);
                    FMA2(a1[i][0], wv.x, z2); FMA2(a1[i][1], wv.y, z2);
                }
            }
            #pragma unroll
            for (int i = 0; i < 4; i++) {
                int bb = rg * 4 + i;
                bool ob = msk[bb] > 0.0f;
                float2 lo = up2(a1[i][0]), hi = up2(a1[i][1]);
                float vals[4] = { lo.x, lo.y, hi.x, hi.y };
                int o0 = ch * 4;
                if (ch < 16) {
                    float2 hA = *(const float2*)&hs[bb * 66 + o0];
                    float2 hB = *(const float2*)&hs[bb * 66 + o0 + 2];
                    float g0 = 1.0f / (1.0f + __expf(-(vals[0] + gb[o0 + 0])));
                    float g1 = 1.0f / (1.0f + __expf(-(vals[1] + gb[o0 + 1])));
                    float g2 = 1.0f / (1.0f + __expf(-(vals[2] + gb[o0 + 2])));
                    float g3 = 1.0f / (1.0f + __expf(-(vals[3] + gb[o0 + 3])));
                    float4 h1v;
                    h1v.x = ob ? g0 * hA.x : hA.x;
                    h1v.y = ob ? g1 * hA.y : hA.y;
                    h1v.z = ob ? g2 * hB.x : hB.x;
                    h1v.w = ob ? g3 * hB.y : hB.y;
                    *(float4*)&h1s[bb * 64 + o0] = h1v;
                } else {
                    int d0 = o0 - 64;
                    float4 uv;
                    uv.x = 1.0f / (1.0f + __expf(-(vals[0] + gb[o0 + 0])));
                    uv.y = 1.0f / (1.0f + __expf(-(vals[1] + gb[o0 + 1])));
                    uv.z = 1.0f / (1.0f + __expf(-(vals[2] + gb[o0 + 2])));
                    uv.w = 1.0f / (1.0f + __expf(-(vals[3] + gb[o0 + 3])));
                    *(float4*)&us[bb * 64 + d0] = uv;
                }
            }
            __syncthreads();

            // zs2 = [x, h1]
            for (int idx = tid; idx < 32 * CP; idx += 256) {
                int b2 = idx / CP, c = idx - b2 * CP;
                float v = 0.0f;
                if (c < Dn)       v = obs[(((size_t)b2 * Tn + t) * Nn + n) * Dn + c];
                else if (c == Dn) v = g_rar[(b2 * Tn + t) * Nn + n];
                else if (c < Cn)  v = h1s[b2 * 64 + (c - Dn - 1)];
                zs[idx] = v;
            }
            __syncthreads();

            // ---- cand GEMM ----
            int ch2 = 32 + 2 * w + (lane & 1);
            int bg  = lane >> 1;
            unsigned long long a2[2][2];
            a2[0][0] = 0ull; a2[0][1] = 0ull; a2[1][0] = 0ull; a2[1][1] = 0ull;
            const float* zb2 = zs + bg * 2 * CP;
            #pragma unroll 1
            for (int c4 = 0; c4 < 32; c4++) {
                float4 z4[2];
                z4[0] = *(const float4*)(zb2 + c4 * 4);
                z4[1] = *(const float4*)(zb2 + CP + c4 * 4);
                #pragma unroll
                for (int cc = 0; cc < 4; cc++) {
                    ulonglong2 wv = *(const ulonglong2*)(gWs + (c4 * 4 + cc) * G3 + ch2 * 4);
                    #pragma unroll
                    for (int i = 0; i < 2; i++) {
                        unsigned long long z2 = pk2(f4c(z4[i], cc));
                        FMA2(a2[i][0], wv.x, z2); FMA2(a2[i][1], wv.y, z2);
                    }
                }
            }
            {
                ulonglong2 wv = *(const ulonglong2*)(gWs + 128 * G3 + ch2 * 4);
                #pragma unroll
                for (int i = 0; i < 2; i++) {
                    unsigned long long z2 = pk2(zb2[i * CP + 128]);
                    FMA2(a2[i][0], wv.x, z2); FMA2(a2[i][1], wv.y, z2);
                }
            }
            __syncthreads();   // gWs reads done -> safe to overwrite OV

            // prefetch next A' qkv weights into OV (overlaps epilogue)
            if (t < Tn - 1) {
                for (int idx = tid; idx < 129 * 88; idx += 256) {
                    int row = idx / 88, col = idx - row * 88;
                    cpa16(ov_u + (unsigned)(row * WCOLS + col * 4) * 4,
                          g_WT2 + row * WCOLS + col * 4);
                }
                CP_COMMIT();
            }

            // final epilogue: h2 -> hs (+ out when final step of sample)
            #pragma unroll
            for (int i = 0; i < 2; i++) {
                int bb = bg * 2 + i;
                bool ob = msk[bb] > 0.0f;
                bool fin = (t == lengths[bb] - 1);
                int d0 = (ch2 - 32) * 4;
                float2 lo = up2(a2[i][0]), hi = up2(a2[i][1]);
                float vals[4] = { lo.x, lo.y, hi.x, hi.y };
                float4 h1v = *(const float4*)&h1s[bb * 64 + d0];
                float4 uv  = *(const float4*)&us[bb * 64 + d0];
                float4 h2;
                float c0 = tanhf(vals[0] + gb[128 + d0 + 0]);
                float c1 = tanhf(vals[1] + gb[128 + d0 + 1]);
                float c2 = tanhf(vals[2] + gb[128 + d0 + 2]);
                float c3 = tanhf(vals[3] + gb[128 + d0 + 3]);
                h2.x = ob ? (1.0f - uv.x) * h1v.x + uv.x * c0 : h1v.x;
                h2.y = ob ? (1.0f - uv.y) * h1v.y + uv.y * c1 : h1v.y;
                h2.z = ob ? (1.0f - uv.z) * h1v.z + uv.z * c2 : h1v.z;
                h2.w = ob ? (1.0f - uv.w) * h1v.w + uv.w * c3 : h1v.w;
                *(float2*)&hs[bb * 66 + d0]     = make_float2(h2.x, h2.y);
                *(float2*)&hs[bb * 66 + d0 + 2] = make_float2(h2.z, h2.w);
                if (fin) *(float4*)&out[((size_t)bb * Nn + n) * Dn + d0] = h2;
            }
            __syncthreads();   // hs writes + scr reads done before next A' comb
        }
    }
}

// ---------------- launcher ----------------
extern "C" void kernel_launch(void* const* d_in, const int* in_sizes, int n_in,
                              void* d_out, int out_size) {
    (void)n_in; (void)out_size;
    const float* obs   = (const float*)d_in[0];
    const float* maskp = (const float*)d_in[1];
    const float* avg   = (const float*)d_in[2];
    const float* plm   = (const float*)d_in[3];
    const int* lengths;
    int off;
    if (in_sizes[4] == Bn) { lengths = (const int*)d_in[4];  off = 5; }
    else                   { lengths = (const int*)d_in[25]; off = 4; }
    const float* rarW  = (const float*)d_in[off + 0];
    const float* pfW1  = (const float*)d_in[off + 1];
    const float* pfb1  = (const float*)d_in[off + 2];
    const float* pfW2  = (const float*)d_in[off + 3];
    const float* pfb2  = (const float*)d_in[off + 4];
    const float* pgW1  = (const float*)d_in[off + 5];
    const float* pgb1  = (const float*)d_in[off + 6];
    const float* pgW2  = (const float*)d_in[off + 7];
    const float* pgb2  = (const float*)d_in[off + 8];
    const float* rstW  = (const float*)d_in[off + 9];
    const float* rstB  = (const float*)d_in[off + 10];
    const float* updW  = (const float*)d_in[off + 11];
    const float* updB  = (const float*)d_in[off + 12];
    const float* candW = (const float*)d_in[off + 13];
    const float* candB = (const float*)d_in[off + 14];
    const float* qW    = (const float*)d_in[off + 15];
    const float* qb    = (const float*)d_in[off + 16];
    const float* kW    = (const float*)d_in[off + 17];
    const float* kb    = (const float*)d_in[off + 18];
    const float* vW    = (const float*)d_in[off + 19];
    const float* vb    = (const float*)d_in[off + 20];
    float* outp = (float*)d_out;

    cudaFuncSetAttribute(k_main, cudaFuncAttributeMaxDynamicSharedMemorySize, SMEM_B);

    k_pre0<<<Bn, Nn>>>(maskp, avg);
    k_pre1<<<Nn, 128>>>(plm, pfW1, pfb1, pfW2, pfb2, pgW1, pgb1, pgW2, pgb2);
    k_pre2<<<Nn, Nn>>>();
    k_pre3<<<Nn, 256>>>(rstW, rstB, updW, updB, candW, candB);
    k_pre4<<<Cn, WCOLS>>>(qW, qb, kW, kb, vW, vb);

    k_main<<<NCTA, 256, SMEM_B>>>(obs, maskp, rarW, lengths, outp);
}

// round 10
// speedup vs baseline: 2.4842x; 1.0125x over previous
#include <cuda_runtime.h>
#include <cstdint>

#define Bn   32
#define Tn   64
#define Nn   128
#define Dn   64
#define Cn   129
#define CP   132
#define QDn  5
#define NEn  8
#define PLMn 768
#define G3   192
#define NEGV (-9e15f)

#define WCOLS 352          // global qkv weight row stride
#define WSTR  344          // smem qkv weight row stride (86 chunks)
#define VROW  264          // g_V row: h0 [0,129), pad, h1 [132,261)
#define NCTA  128u

// ---------------- device scratch ----------------
__device__ __align__(16) float g_qv[Nn * QDn];
__device__ __align__(16) float g_ne[Nn * NEn];
__device__ __align__(16) float g_adj[Nn * Nn];
__device__ __align__(16) float g_rar[Bn * Tn * Nn];
__device__ __align__(16) float g_gW[Nn * Cn * G3];
__device__ __align__(16) float g_gB[Nn * G3];
__device__ __align__(16) float g_WT2[Cn * WCOLS];
__device__ __align__(16) float g_bT[WCOLS];
__device__ __align__(16) float g_Q[2 * Bn * Nn * 32];
__device__ __align__(16) float g_K[2 * Bn * Nn * 32];
__device__ __align__(16) float g_V[2 * (size_t)Bn * Nn * VROW];
__device__ __align__(16) float g_att[(size_t)Bn * Nn * CP];

__device__ unsigned g_ctrG;
__device__ unsigned g_ctrGrp[4];

// ---------------- helpers ----------------
#define FMA2(acc, w, z) asm("fma.rn.f32x2 %0, %1, %2, %0;" : "+l"(acc) : "l"(w), "l"(z))

__device__ __forceinline__ unsigned long long pk2(float z) {
    unsigned long long r;
    asm("mov.b64 %0, {%1, %1};" : "=l"(r) : "f"(z));
    return r;
}
__device__ __forceinline__ float2 up2(unsigned long long v) {
    float2 r;
    asm("mov.b64 {%0, %1}, %2;" : "=f"(r.x), "=f"(r.y) : "l"(v));
    return r;
}
__device__ __forceinline__ float f4c(const float4& v, int cc) {
    return cc == 0 ? v.x : cc == 1 ? v.y : cc == 2 ? v.z : v.w;
}
__device__ __forceinline__ void cpa16(unsigned dst, const void* src) {
    asm volatile("cp.async.cg.shared.global [%0], [%1], 16;" :: "r"(dst), "l"(src));
}
#define CP_COMMIT() asm volatile("cp.async.commit_group;" ::: "memory")
#define CP_WAIT(N)  asm volatile("cp.async.wait_group %0;" :: "n"(N) : "memory")

__device__ __forceinline__ float fsigmoid(float x) {
    return __fdividef(1.0f, 1.0f + __expf(-x));
}
__device__ __forceinline__ float ftanh(float x) {
    return 1.0f - 2.0f * __fdividef(1.0f, __expf(2.0f * x) + 1.0f);
}

// ---------------- precompute (fused to 3 kernels) ----------------
__global__ void k_preA(const float* __restrict__ maskp, const float* __restrict__ avg,
                       const float* __restrict__ plm,
                       const float* __restrict__ pfW1, const float* __restrict__ pfb1,
                       const float* __restrict__ pfW2, const float* __restrict__ pfb2,
                       const float* __restrict__ pgW1, const float* __restrict__ pgb1,
                       const float* __restrict__ pgW2, const float* __restrict__ pgb2) {
    __shared__ float h1[128], h2[128];
    __shared__ float nrm;
    if (blockIdx.x < 32) {
        int b = blockIdx.x, n = threadIdx.x;
        int gtid = b * 128 + n;
        if (gtid == 0) g_ctrG = 0;
        if (gtid < 4)  g_ctrGrp[gtid] = 0;
        float s = 0.0f;
        for (int t = 0; t < Tn; t++) s += maskp[(b * Tn + t) * Nn + n];
        float inv = 1.0f / (s + 1.0f);
        for (int t = 0; t < Tn; t++)
            g_rar[(b * Tn + t) * Nn + n] = 0.5f * tanhf(avg[(b * Tn + t) * Nn + n] * inv);
        return;
    }
    int n = blockIdx.x - 32, j = threadIdx.x;
    const float* p = plm + (size_t)n * PLMn;
    float a = 0.0f, bv = 0.0f;
    for (int c = 0; c < PLMn; c++) {
        float pv = p[c];
        a  += pv * pfW1[c * 128 + j];
        bv += pv * pgW1[c * 128 + j];
    }
    a += pfb1[j]; bv += pgb1[j];
    h1[j] = a  > 0.0f ? a  : 0.0f;
    h2[j] = bv > 0.0f ? bv : 0.0f;
    __syncthreads();
    if (j < QDn) {
        float s = pfb2[j];
        for (int c = 0; c < 128; c++) s += h1[c] * pfW2[c * QDn + j];
        g_qv[n * QDn + j] = s;
    }
    if (j < NEn) {
        float s = pgb2[j];
        for (int c = 0; c < 128; c++) s += h2[c] * pgW2[c * NEn + j];
        g_ne[n * NEn + j] = s;
    }
    __syncthreads();
    if (j == 0) {
        float s = 0.0f;
        for (int e = 0; e < NEn; e++) { float v = g_ne[n * NEn + e]; s += v * v; }
        nrm = fmaxf(sqrtf(s), 1e-12f);
    }
    __syncthreads();
    if (j < NEn) g_ne[n * NEn + j] /= nrm;
}

__global__ void k_pre2() {
    int n = blockIdx.x, m = threadIdx.x;
    __shared__ float red[128];
    float s = 0.0f;
    for (int e = 0; e < NEn; e++) s += g_ne[n * NEn + e] * g_ne[m * NEn + e];
    red[m] = s;
    __syncthreads();
    for (int st = 64; st > 0; st >>= 1) { if (m < st) red[m] = fmaxf(red[m], red[m + st]); __syncthreads(); }
    float mx = red[0];
    __syncthreads();
    float e = expf(s - mx);
    red[m] = e;
    __syncthreads();
    for (int st = 64; st > 0; st >>= 1) { if (m < st) red[m] += red[m + st]; __syncthreads(); }
    g_adj[n * Nn + m] = e / red[0];
}

__global__ void k_preB(const float* __restrict__ rstW, const float* __restrict__ rstB,
                       const float* __restrict__ updW, const float* __restrict__ updB,
                       const float* __restrict__ candW, const float* __restrict__ candB,
                       const float* __restrict__ qW, const float* __restrict__ qb,
                       const float* __restrict__ kW, const float* __restrict__ kb,
                       const float* __restrict__ vW, const float* __restrict__ vb) {
    __shared__ float qv[QDn];
    if (blockIdx.x < 128) {
        int n = blockIdx.x;
        if (threadIdx.x < QDn) qv[threadIdx.x] = g_qv[n * QDn + threadIdx.x];
        __syncthreads();
        for (int idx = threadIdx.x; idx < Cn * Dn; idx += blockDim.x) {
            int c = idx / Dn, o = idx % Dn;
            float r = 0.0f, u = 0.0f, cd = 0.0f;
            for (int q = 0; q < QDn; q++) {
                float s = qv[q];
                int off = (q * Cn + c) * Dn + o;
                r  += s * rstW[off];
                u  += s * updW[off];
                cd += s * candW[off];
            }
            float* dst = g_gW + ((size_t)n * Cn + c) * G3;
            dst[o] = r; dst[64 + o] = u; dst[128 + o] = cd;
        }
        for (int o = threadIdx.x; o < Dn; o += blockDim.x) {
            float r = 0.0f, u = 0.0f, cd = 0.0f;
            for (int q = 0; q < QDn; q++) {
                float s = qv[q];
                r  += s * rstB[q * Dn + o];
                u  += s * updB[q * Dn + o];
                cd += s * candB[q * Dn + o];
            }
            g_gB[n * G3 + o] = r; g_gB[n * G3 + 64 + o] = u; g_gB[n * G3 + 128 + o] = cd;
        }
        return;
    }
    // qkv weight transpose: Q[0,32) K[32,64) Vh0[64,193) pad Vh1[196,325)
    int c = blockIdx.x - 128;
    int j = threadIdx.x;
    float w = 0.0f, bv = 0.0f;
    if (j < 32) {
        int h = j >> 4, kk = j & 15;
        w = qW[(h * Cn + c) * 16 + kk]; bv = qb[h * 16 + kk];
    } else if (j < 64) {
        int jj = j - 32; int h = jj >> 4, kk = jj & 15;
        w = kW[(h * Cn + c) * 16 + kk]; bv = kb[h * 16 + kk];
    } else if (j <= 192) {
        int d = j - 64;
        w = vW[((size_t)c) * Cn + d]; bv = vb[d];
    } else if (j >= 196 && j <= 324) {
        int d = j - 196;
        w = vW[((size_t)(Cn + c)) * Cn + d]; bv = vb[Cn + d];
    }
    g_WT2[c * WCOLS + j] = w;
    if (c == 0) g_bT[j] = bv;
}

// ---------------- group barrier ----------------
__device__ __forceinline__ void gsync(unsigned* ctr, unsigned target) {
    __syncthreads();
    if (threadIdx.x == 0) {
        __threadfence();
        atomicAdd(ctr, 1u);
        while (*(volatile unsigned*)ctr < target) { }
        __threadfence();
    }
    __syncthreads();
}

// ---------------- smem layout (floats) ----------------
// OV  [0, 44376)   A': qkv W (129x344) / B: Vs (128x264) / C: gW (129x192)
// SCR [44376, +10624)  per-phase scratch
// HS  resident h 32x66 ; SB qkv bias 328
#define OV_F   (Cn * WSTR)              // 44376
#define SCR_F  10624
#define HS_OFF (OV_F + SCR_F)           // 55000
#define SB_OFF (HS_OFF + 2112)          // 57112
#define SMEM_FLOATS (SB_OFF + 328)      // 57440
#define SMEM_B (SMEM_FLOATS * 4)        // 229760 bytes

__global__ void __launch_bounds__(256, 1) k_main(const float* __restrict__ obs,
                                                 const float* __restrict__ maskp,
                                                 const float* __restrict__ rarW,
                                                 const int* __restrict__ lengths,
                                                 float* __restrict__ out) {
    extern __shared__ float sm[];
    float* OV    = sm;
    float* scr   = sm + OV_F;
    float* hs    = sm + HS_OFF;
    float* sBias = sm + SB_OFF;

    unsigned sm_u  = (unsigned)__cvta_generic_to_shared(sm);
    unsigned ov_u  = sm_u;
    unsigned scr_u = sm_u + OV_F * 4;

    int tid = threadIdx.x;
    int cid = blockIdx.x;
    int n   = cid;
    int b   = cid & 31, n0 = (cid >> 5) * 32;
    int grp = cid >> 5;

    int w = tid >> 5, lane = tid & 31;
    int rg = lane >> 2, co = lane & 3;
    int ch0 = 11 * w + co;
    int ch8 = lane >> 2, lr = lane & 3;   // (chunk, row) mapping for C

    for (int i = tid; i < 2112; i += 256) hs[i] = 0.0f;
    for (int i = tid; i < 328; i += 256) sBias[i] = g_bT[i];
    __syncthreads();

    // prefetch qkv weights for A'(0)
    for (int idx = tid; idx < 129 * 86; idx += 256) {
        int row = idx / 86, col = idx - row * 86;
        cpa16(ov_u + (unsigned)(row * WSTR + col * 4) * 4, g_WT2 + row * WCOLS + col * 4);
    }
    CP_COMMIT();

    for (int tt = 0; tt <= Tn; tt++) {
        // ================= Phase A'(tt): node-major qkv =================
        if (tt < Tn) {
            int buf = tt & 1;
            float* comb = scr;   // 32 x 132
            for (int idx = tid; idx < 32 * CP; idx += 256) {
                int bb = idx / CP, c = idx - bb * CP;
                float v = 0.0f;
                if (c < Dn)       v = obs[(((size_t)bb * Tn + tt) * Nn + n) * Dn + c];
                else if (c == Dn) v = g_rar[(bb * Tn + tt) * Nn + n];
                else if (c < Cn)  v = hs[bb * 66 + (c - Dn - 1)];
                comb[idx] = v;
            }
            CP_WAIT(0);
            __syncthreads();

            unsigned long long acc[4][3][2];
            #pragma unroll
            for (int i = 0; i < 4; i++)
                #pragma unroll
                for (int j = 0; j < 3; j++) { acc[i][j][0] = 0ull; acc[i][j][1] = 0ull; }

            const float* zb = comb + rg * 4 * CP;
            #pragma unroll 1
            for (int c4 = 0; c4 < 32; c4++) {
                float4 z4[4];
                #pragma unroll
                for (int i = 0; i < 4; i++) z4[i] = *(const float4*)(zb + i * CP + c4 * 4);
                #pragma unroll
                for (int cc = 0; cc < 4; cc++) {
                    const float* wr = OV + (c4 * 4 + cc) * WSTR + ch0 * 4;
                    ulonglong2 w0 = *(const ulonglong2*)(wr);
                    ulonglong2 w1 = *(const ulonglong2*)(wr + 16);
                    ulonglong2 w2 = *(const ulonglong2*)(wr + 32);
                    #pragma unroll
                    for (int i = 0; i < 4; i++) {
                        unsigned long long z2 = pk2(f4c(z4[i], cc));
                        FMA2(acc[i][0][0], w0.x, z2); FMA2(acc[i][0][1], w0.y, z2);
                        FMA2(acc[i][1][0], w1.x, z2); FMA2(acc[i][1][1], w1.y, z2);
                        FMA2(acc[i][2][0], w2.x, z2); FMA2(acc[i][2][1], w2.y, z2);
                    }
                }
            }
            {   // c = 128
                const float* wr = OV + 128 * WSTR + ch0 * 4;
                ulonglong2 w0 = *(const ulonglong2*)(wr);
                ulonglong2 w1 = *(const ulonglong2*)(wr + 16);
                ulonglong2 w2 = *(const ulonglong2*)(wr + 32);
                #pragma unroll
                for (int i = 0; i < 4; i++) {
                    unsigned long long z2 = pk2(zb[i * CP + 128]);
                    FMA2(acc[i][0][0], w0.x, z2); FMA2(acc[i][0][1], w0.y, z2);
                    FMA2(acc[i][1][0], w1.x, z2); FMA2(acc[i][1][1], w1.y, z2);
                    FMA2(acc[i][2][0], w2.x, z2); FMA2(acc[i][2][1], w2.y, z2);
                }
            }
            float* Qb = g_Q + (size_t)buf * Bn * Nn * 32;
            float* Kb = g_K + (size_t)buf * Bn * Nn * 32;
            float* Vb = g_V + (size_t)buf * Bn * Nn * VROW;
            #pragma unroll
            for (int i = 0; i < 4; i++) {
                int bb = rg * 4 + i;
                #pragma unroll
                for (int j = 0; j < 3; j++) {
                    if (co + 4 * j > 10) continue;
                    int ch = ch0 + 4 * j;
                    if (ch >= 82) continue;
                    float2 lo = up2(acc[i][j][0]), hi = up2(acc[i][j][1]);
                    float4 bias4 = *(const float4*)&sBias[ch * 4];
                    float4 v4 = make_float4(lo.x + bias4.x, lo.y + bias4.y,
                                            hi.x + bias4.z, hi.y + bias4.w);
                    if (ch < 8)        *(float4*)&Qb[((size_t)bb * Nn + n) * 32 + ch * 4] = v4;
                    else if (ch < 16)  *(float4*)&Kb[((size_t)bb * Nn + n) * 32 + ch * 4 - 32] = v4;
                    else               *(float4*)&Vb[((size_t)bb * Nn + n) * VROW + ch * 4 - 64] = v4;
                }
            }
        }
        if (tt == Tn) break;
        int t = tt;
        gsync(&g_ctrG, 128u * (t + 1));

        // ================= Phase B: attention (batch-major) =================
        {
            int buf = t & 1;
            float* Vs  = OV;                 // 128 x 264
            float* Ks  = scr;                // 128 x 36
            float* SsT = scr + 4608;         // 128 x 36 (transposed P: [m][row])
            float* Qs  = scr + 9216;         // 32 x 32
            float* rs  = scr + 10240;        // 128
            float* msv = scr + 10368;        // 128
            unsigned* mskw = (unsigned*)(scr + 10496);  // 128 words

            const float* Kg = g_K + (size_t)buf * Bn * Nn * 32 + (size_t)b * Nn * 32;
            const float* Qg = g_Q + (size_t)buf * Bn * Nn * 32 + (size_t)b * Nn * 32;
            const float* Vg = g_V + (size_t)buf * Bn * Nn * VROW + (size_t)b * Nn * VROW;

            for (int idx = tid; idx < 128 * 8; idx += 256) {
                int row = idx >> 3, q = idx & 7;
                cpa16(scr_u + (unsigned)(row * 36 + q * 4) * 4, Kg + row * 32 + q * 4);
            }
            {
                int row = tid >> 3, q = tid & 7;
                cpa16(scr_u + (unsigned)(9216 + row * 32 + q * 4) * 4, Qg + (n0 + row) * 32 + q * 4);
            }
            CP_COMMIT();
            for (int idx = tid; idx < 128 * 66; idx += 256)
                cpa16(ov_u + (unsigned)idx * 16, Vg + idx * 4);
            CP_COMMIT();

            if (tid < 128) {
                rs[tid]  = g_rar[(b * Tn + t) * Nn + tid];
                msv[tid] = maskp[((size_t)b * Tn + t) * Nn + tid];
            }
            __syncthreads();
            if (tid < 128) {
                int r = tid >> 2, ws = tid & 3;
                int nn = n0 + r;
                unsigned word = 0;
                float rn = rs[nn], mn = msv[nn];
                for (int mm = 0; mm < 32; mm++) {
                    int m = ws * 32 + mm;
                    if (nn != m) {
                        float am  = mn * msv[m];
                        float rm  = -rarW[nn * Nn + m] * fabsf(rn - rs[m]);
                        float val = g_adj[nn * Nn + m] * (1.0f + rm) * am;
                        if (val == 0.0f) word |= (1u << mm);
                    }
                }
                mskw[tid] = word;
            }
            CP_WAIT(1);
            __syncthreads();

            int r2 = tid >> 3, c8 = tid & 7;
            int ch = 4 * w + co;
            unsigned long long o[4][2];
            #pragma unroll
            for (int i = 0; i < 4; i++) { o[i][0] = 0ull; o[i][1] = 0ull; }
            float ex = 0.0f;

            for (int h = 0; h < 2; h++) {
                float4 q4[4];
                const float4* qrow = (const float4*)(Qs + r2 * 32 + h * 16);
                q4[0] = qrow[0]; q4[1] = qrow[1]; q4[2] = qrow[2]; q4[3] = qrow[3];

                float sv[16]; float mx = -3.0e38f;
                #pragma unroll
                for (int jm = 0; jm < 16; jm++) {
                    int m = c8 + 8 * jm;
                    const float4* kr = (const float4*)(Ks + m * 36 + h * 16);
                    float d = 0.0f;
                    #pragma unroll
                    for (int kq = 0; kq < 4; kq++) {
                        float4 kv = kr[kq];
                        d += q4[kq].x * kv.x + q4[kq].y * kv.y + q4[kq].z * kv.z + q4[kq].w * kv.w;
                    }
                    d *= 0.25f;
                    d = d > 0.0f ? d : 0.2f * d;
                    if ((mskw[(r2 << 2) + (m >> 5)] >> (m & 31)) & 1u) d = NEGV;
                    sv[jm] = d;
                    mx = fmaxf(mx, d);
                }
                #pragma unroll
                for (int oo = 1; oo < 8; oo <<= 1) mx = fmaxf(mx, __shfl_xor_sync(0xffffffffu, mx, oo));
                float sum = 0.0f;
                #pragma unroll
                for (int jm = 0; jm < 16; jm++) { float ee = __expf(sv[jm] - mx); sv[jm] = ee; sum += ee; }
                #pragma unroll
                for (int oo = 1; oo < 8; oo <<= 1) sum += __shfl_xor_sync(0xffffffffu, sum, oo);
                float inv = 1.0f / sum;
                // transposed store: SsT[m][row]
                #pragma unroll
                for (int jm = 0; jm < 16; jm++) SsT[(c8 + 8 * jm) * 36 + r2] = sv[jm] * inv;
                if (h == 0) { CP_WAIT(0); }
                __syncthreads();

                const float* Vh = Vs + h * 132;
                #pragma unroll 4
                for (int m = 0; m < 128; m++) {
                    float4 pT = *(const float4*)(SsT + m * 36 + rg * 4);
                    ulonglong2 v = *(const ulonglong2*)(Vh + m * VROW + ch * 4);
                    #pragma unroll
                    for (int i = 0; i < 4; i++) {
                        unsigned long long z2 = pk2(f4c(pT, i));
                        FMA2(o[i][0], v.x, z2); FMA2(o[i][1], v.y, z2);
                    }
                }
                {   // column d = 128
                    int row = tid >> 3, sub = tid & 7;
                    float e = 0.0f;
                    #pragma unroll
                    for (int k = 0; k < 16; k++) {
                        int m = sub * 16 + k;
                        e += SsT[m * 36 + row] * Vh[m * VROW + 128];
                    }
                    ex += e;
                }
                __syncthreads();
            }
            #pragma unroll
            for (int i = 0; i < 4; i++) {
                int nn = n0 + rg * 4 + i;
                float2 lo = up2(o[i][0]), hi = up2(o[i][1]);
                float4 a = make_float4(lo.x * 0.5f, lo.y * 0.5f, hi.x * 0.5f, hi.y * 0.5f);
                *(float4*)&g_att[((size_t)b * Nn + nn) * CP + ch * 4] = a;
            }
            ex += __shfl_xor_sync(0xffffffffu, ex, 1);
            ex += __shfl_xor_sync(0xffffffffu, ex, 2);
            ex += __shfl_xor_sync(0xffffffffu, ex, 4);
            if ((tid & 7) == 0)
                g_att[((size_t)b * Nn + n0 + (tid >> 3)) * CP + 128] = ex * 0.5f;
        }
        gsync(&g_ctrGrp[grp], 32u * (t + 1));

        // ================= Phase C: gates (node-major, h in smem) ===========
        {
            float* gWs = OV;              // 129*192
            float* zs  = scr;             // 32*132
            float* h1s = scr + 4224;      // 32*64
            float* us  = h1s + 2048;      // 32*64
            float* gb  = us + 2048;       // 192
            float* msk = gb + 192;        // 32

            const float* gwsrc = g_gW + (size_t)n * Cn * G3;
            for (int idx = tid; idx < Cn * G3 / 4; idx += 256)
                cpa16(ov_u + (unsigned)idx * 16, gwsrc + idx * 4);
            for (int idx = tid; idx < 32 * 33; idx += 256) {
                int b2 = idx / 33, q = idx - b2 * 33;
                cpa16(scr_u + (unsigned)(b2 * CP + q * 4) * 4,
                      g_att + ((size_t)b2 * Nn + n) * CP + q * 4);
            }
            CP_COMMIT();
            if (tid < G3) gb[tid] = g_gB[n * G3 + tid];
            if (tid < 32) msk[tid] = maskp[((size_t)tid * Tn + t) * Nn + n];
            CP_WAIT(0);
            __syncthreads();

            int bb = w * 4 + lr;          // (chunk,row) mapping: lane = ch8 x lr
            bool ob = msk[bb] > 0.0f;

            // ---- r/u GEMM: thread covers batch bb, chunks ch8+8*rep ----
            unsigned long long a1[4][2];
            #pragma unroll
            for (int i = 0; i < 4; i++) { a1[i][0] = 0ull; a1[i][1] = 0ull; }
            const float* zrow = zs + bb * CP;
            #pragma unroll 2
            for (int c = 0; c < Cn; c++) {
                unsigned long long z2 = pk2(zrow[c]);
                const float* wc = gWs + c * G3 + ch8 * 4;
                #pragma unroll
                for (int rep = 0; rep < 4; rep++) {
                    ulonglong2 wv = *(const ulonglong2*)(wc + rep * 32);
                    FMA2(a1[rep][0], wv.x, z2); FMA2(a1[rep][1], wv.y, z2);
                }
            }
            #pragma unroll
            for (int rep = 0; rep < 4; rep++) {
                int o0 = (ch8 + 8 * rep) * 4;
                float2 lo = up2(a1[rep][0]), hi = up2(a1[rep][1]);
                float g0 = fsigmoid(lo.x + gb[o0 + 0]);
                float g1 = fsigmoid(lo.y + gb[o0 + 1]);
                float g2 = fsigmoid(hi.x + gb[o0 + 2]);
                float g3 = fsigmoid(hi.y + gb[o0 + 3]);
                if (rep < 2) {
                    float2 hA = *(const float2*)&hs[bb * 66 + o0];
                    float2 hB = *(const float2*)&hs[bb * 66 + o0 + 2];
                    float4 h1v;
                    h1v.x = ob ? g0 * hA.x : hA.x;
                    h1v.y = ob ? g1 * hA.y : hA.y;
                    h1v.z = ob ? g2 * hB.x : hB.x;
                    h1v.w = ob ? g3 * hB.y : hB.y;
                    *(float4*)&h1s[bb * 64 + o0] = h1v;
                } else {
                    *(float4*)&us[bb * 64 + (o0 - 64)] = make_float4(g0, g1, g2, g3);
                }
            }
            __syncthreads();

            // zs2 = [x, h1]
            for (int idx = tid; idx < 32 * CP; idx += 256) {
                int b2 = idx / CP, c = idx - b2 * CP;
                float v = 0.0f;
                if (c < Dn)       v = obs[(((size_t)b2 * Tn + t) * Nn + n) * Dn + c];
                else if (c == Dn) v = g_rar[(b2 * Tn + t) * Nn + n];
                else if (c < Cn)  v = h1s[b2 * 64 + (c - Dn - 1)];
                zs[idx] = v;
            }
            __syncthreads();

            // ---- cand GEMM: thread covers batch bb, chunks 32+ch8+8*rep ----
            unsigned long long a2[2][2];
            a2[0][0] = 0ull; a2[0][1] = 0ull; a2[1][0] = 0ull; a2[1][1] = 0ull;
            #pragma unroll 2
            for (int c = 0; c < Cn; c++) {
                unsigned long long z2 = pk2(zrow[c]);
                const float* wc = gWs + c * G3 + 128 + ch8 * 4;
                #pragma unroll
                for (int rep = 0; rep < 2; rep++) {
                    ulonglong2 wv = *(const ulonglong2*)(wc + rep * 32);
                    FMA2(a2[rep][0], wv.x, z2); FMA2(a2[rep][1], wv.y, z2);
                }
            }
            __syncthreads();   // gWs reads done

            // prefetch next A' qkv weights (overlaps epilogue)
            if (t < Tn - 1) {
                for (int idx = tid; idx < 129 * 86; idx += 256) {
                    int row = idx / 86, col = idx - row * 86;
                    cpa16(ov_u + (unsigned)(row * WSTR + col * 4) * 4,
                          g_WT2 + row * WCOLS + col * 4);
                }
                CP_COMMIT();
            }

            bool fin = (t == lengths[bb] - 1);
            #pragma unroll
            for (int rep = 0; rep < 2; rep++) {
                int d0 = (ch8 + 8 * rep) * 4;
                float2 lo = up2(a2[rep][0]), hi = up2(a2[rep][1]);
                float c0 = ftanh(lo.x + gb[128 + d0 + 0]);
                float c1 = ftanh(lo.y + gb[128 + d0 + 1]);
                float c2 = ftanh(hi.x + gb[128 + d0 + 2]);
                float c3 = ftanh(hi.y + gb[128 + d0 + 3]);
                float4 h1v = *(const float4*)&h1s[bb * 64 + d0];
                float4 uv  = *(const float4*)&us[bb * 64 + d0];
                float4 h2;
                h2.x = ob ? (1.0f - uv.x) * h1v.x + uv.x * c0 : h1v.x;
                h2.y = ob ? (1.0f - uv.y) * h1v.y + uv.y * c1 : h1v.y;
                h2.z = ob ? (1.0f - uv.z) * h1v.z + uv.z * c2 : h1v.z;
                h2.w = ob ? (1.0f - uv.w) * h1v.w + uv.w * c3 : h1v.w;
                *(float2*)&hs[bb * 66 + d0]     = make_float2(h2.x, h2.y);
                *(float2*)&hs[bb * 66 + d0 + 2] = make_float2(h2.z, h2.w);
                if (fin) *(float4*)&out[((size_t)bb * Nn + n) * Dn + d0] = h2;
            }
            __syncthreads();
        }
    }
}

// ---------------- launcher ----------------
extern "C" void kernel_launch(void* const* d_in, const int* in_sizes, int n_in,
                              void* d_out, int out_size) {
    (void)n_in; (void)out_size;
    const float* obs   = (const float*)d_in[0];
    const float* maskp = (const float*)d_in[1];
    const float* avg   = (const float*)d_in[2];
    const float* plm   = (const float*)d_in[3];
    const int* lengths;
    int off;
    if (in_sizes[4] == Bn) { lengths = (const int*)d_in[4];  off = 5; }
    else                   { lengths = (const int*)d_in[25]; off = 4; }
    const float* rarW  = (const float*)d_in[off + 0];
    const float* pfW1  = (const float*)d_in[off + 1];
    const float* pfb1  = (const float*)d_in[off + 2];
    const float* pfW2  = (const float*)d_in[off + 3];
    const float* pfb2  = (const float*)d_in[off + 4];
    const float* pgW1  = (const float*)d_in[off + 5];
    const float* pgb1  = (const float*)d_in[off + 6];
    const float* pgW2  = (const float*)d_in[off + 7];
    const float* pgb2  = (const float*)d_in[off + 8];
    const float* rstW  = (const float*)d_in[off + 9];
    const float* rstB  = (const float*)d_in[off + 10];
    const float* updW  = (const float*)d_in[off + 11];
    const float* updB  = (const float*)d_in[off + 12];
    const float* candW = (const float*)d_in[off + 13];
    const float* candB = (const float*)d_in[off + 14];
    const float* qW    = (const float*)d_in[off + 15];
    const float* qb    = (const float*)d_in[off + 16];
    const float* kW    = (const float*)d_in[off + 17];
    const float* kb    = (const float*)d_in[off + 18];
    const float* vW    = (const float*)d_in[off + 19];
    const float* vb    = (const float*)d_in[off + 20];
    float* outp = (float*)d_out;

    cudaFuncSetAttribute(k_main, cudaFuncAttributeMaxDynamicSharedMemorySize, SMEM_B);

    k_preA<<<160, 128>>>(maskp, avg, plm, pfW1, pfb1, pfW2, pfb2, pgW1, pgb1, pgW2, pgb2);
    k_pre2<<<Nn, Nn>>>();
    k_preB<<<257, 352>>>(rstW, rstB, updW, updB, candW, candB, qW, qb, kW, kb, vW, vb);

    k_main<<<NCTA, 256, SMEM_B>>>(obs, maskp, rarW, lengths, outp);
}